// round 6
// baseline (speedup 1.0000x reference)
#include <cuda_runtime.h>
#include <cuda_bf16.h>
#include <math.h>
#include <float.h>
#include <string.h>
#include <stdint.h>

#define KNN_K 32
typedef __nv_bfloat16 bf16;

// ---------------- scratch ----------------
__device__ __align__(16) float g_q[2048*2048];        // fp32 q (R0-identical numerics)
__device__ __align__(16) float g_scores[2048*4096];
__device__ __align__(16) bf16 g_x3[3][2048*1024];     // x splits (gate GEMM uses [0],[1])
__device__ __align__(16) bf16 g_ws2[2][512*1024];
__device__ __align__(16) bf16 g_wv2[2][1024*512];
__device__ __align__(16) bf16 g_h2[2][2048*512];
__device__ __align__(16) float g_ts[2048*8*32];
__device__ int   g_ti[2048*8*32];
__device__ __align__(16) float g_cw[2048*4*32];
__device__ int   g_ci[2048*4*32];
__device__ __align__(16) float g_gate[2048*512];

// ---------------- helpers ----------------
__device__ __forceinline__ uint32_t smem_u32(const void* p){ return (uint32_t)__cvta_generic_to_shared(p); }
__device__ __forceinline__ void cp16(uint32_t dst, const void* src){
    asm volatile("cp.async.cg.shared.global [%0], [%1], 16;\n" :: "r"(dst), "l"(src));
}
__device__ __forceinline__ void cp_commit(){ asm volatile("cp.async.commit_group;\n" ::: "memory"); }
template<int N> __device__ __forceinline__ void cp_wait(){ asm volatile("cp.async.wait_group %0;\n" :: "n"(N) : "memory"); }
__device__ __forceinline__ void ldsm4(uint32_t (&r)[4], uint32_t addr){
    asm volatile("ldmatrix.sync.aligned.m8n8.x4.shared.b16 {%0,%1,%2,%3}, [%4];"
        : "=r"(r[0]), "=r"(r[1]), "=r"(r[2]), "=r"(r[3]) : "r"(addr));
}
__device__ __forceinline__ void mma16816(float (&d)[4], const uint32_t (&a)[4], uint32_t b0, uint32_t b1){
    asm volatile("mma.sync.aligned.m16n8k16.row.col.f32.bf16.bf16.f32 "
        "{%0,%1,%2,%3}, {%4,%5,%6,%7}, {%8,%9}, {%0,%1,%2,%3};"
        : "+f"(d[0]), "+f"(d[1]), "+f"(d[2]), "+f"(d[3])
        : "r"(a[0]), "r"(a[1]), "r"(a[2]), "r"(a[3]), "r"(b0), "r"(b1));
}
__device__ __forceinline__ void ffma2(uint64_t& d, uint64_t a, uint64_t b){
    asm("fma.rn.f32x2 %0, %1, %2, %3;" : "=l"(d) : "l"(a), "l"(b), "l"(d));
}
__device__ __forceinline__ void split2v(float v, bf16& h, bf16& l){
    h = __float2bfloat16(v);
    l = __float2bfloat16(v - __bfloat162float(h));
}

// ---------------- fp32 GEMM via packed f32x2 (bitwise == R0 scalar fp32) ----------------
// C = A @ B (+bias) with BT: B is [N][K] row-major -> C = A @ B^T
template<bool BT>
__global__ __launch_bounds__(256) void gemm_f2(
    const float* __restrict__ A, const float* __restrict__ B,
    const float* __restrict__ bias, float* __restrict__ C,
    int K, int lda, int ldb, int ldc, long sA, long sB, long sC)
{
    constexpr int BM = 128, BN = 64, BK = 16;
    __shared__ float As[BK][BM];
    __shared__ float Bs2[BK][BN * 2];     // duplicated pairs {v,v}

    A += (long)blockIdx.z * sA;
    B += (long)blockIdx.z * sB;
    C += (long)blockIdx.z * sC;

    const int bm = blockIdx.y * BM, bn = blockIdx.x * BN;
    const int tid = threadIdx.x;
    const int tx = tid & 15;   // 4 cols
    const int ty = tid >> 4;   // 8 rows

    uint64_t acc2[4][4];
#pragma unroll
    for (int i = 0; i < 4; i++)
#pragma unroll
        for (int j = 0; j < 4; j++) acc2[i][j] = 0ull;

    for (int k0 = 0; k0 < K; k0 += BK){
        // A tile 128x16 -> As[k][m]
#pragma unroll
        for (int it = 0; it < 2; it++){
            int r = (tid >> 2) + it * 64;
            int c = (tid & 3) * 4;
            float4 a4 = *(const float4*)(A + (long)(bm + r) * lda + k0 + c);
            As[c + 0][r] = a4.x; As[c + 1][r] = a4.y;
            As[c + 2][r] = a4.z; As[c + 3][r] = a4.w;
        }
        if (BT){
            int r = tid >> 2;              // 0..63
            int c = (tid & 3) * 4;
            float4 b4 = *(const float4*)(B + (long)(bn + r) * ldb + k0 + c);
            const float bv[4] = {b4.x, b4.y, b4.z, b4.w};
#pragma unroll
            for (int u = 0; u < 4; u++)
                *(float2*)&Bs2[c + u][2 * r] = make_float2(bv[u], bv[u]);
        } else {
            int kk = tid >> 4;             // 0..15
            int c  = (tid & 15) * 4;
            float4 b4 = *(const float4*)(B + (long)(k0 + kk) * ldb + bn + c);
            const float bv[4] = {b4.x, b4.y, b4.z, b4.w};
#pragma unroll
            for (int u = 0; u < 4; u++)
                *(float2*)&Bs2[kk][2 * (c + u)] = make_float2(bv[u], bv[u]);
        }
        __syncthreads();

#pragma unroll
        for (int kk = 0; kk < BK; kk++){
            uint64_t a2[4], b2[4];
            *(uint4*)&a2[0] = *(const uint4*)&As[kk][ty * 8];       // rows pairs {0,1},{2,3}
            *(uint4*)&a2[2] = *(const uint4*)&As[kk][ty * 8 + 4];   // {4,5},{6,7}
            *(uint4*)&b2[0] = *(const uint4*)&Bs2[kk][tx * 8];      // dup cols 0,1
            *(uint4*)&b2[2] = *(const uint4*)&Bs2[kk][tx * 8 + 4];  // dup cols 2,3
#pragma unroll
            for (int i = 0; i < 4; i++)
#pragma unroll
                for (int j = 0; j < 4; j++)
                    ffma2(acc2[i][j], a2[i], b2[j]);
        }
        __syncthreads();
    }

#pragma unroll
    for (int i2 = 0; i2 < 4; i2++){
#pragma unroll
        for (int j = 0; j < 4; j++){
            float2 p; memcpy(&p, &acc2[i2][j], 8);
            int col = bn + tx * 4 + j;
            float b = bias ? bias[col] : 0.0f;
            int r0 = bm + ty * 8 + i2 * 2;
            C[(long)r0 * ldc + col]       = p.x + b;
            C[(long)(r0 + 1) * ldc + col] = p.y + b;
        }
    }
}

// ---------------- HMMA 2-split GEMM (smooth paths only): C = A @ B^T ----------------
// OUTMODE: 0 = fp32 (+bias), 1 = fp32 silu(+bias)
template<int OUTMODE>
__global__ __launch_bounds__(256, 1) void gemm_mma(
    const bf16* __restrict__ A0, const bf16* __restrict__ A1,
    const bf16* __restrict__ B0, const bf16* __restrict__ B1,
    const float* __restrict__ bias, float* __restrict__ C,
    int K, int lda, int ldb, int ldc)
{
    extern __shared__ char dsm[];
    const int tid = threadIdx.x, wid = tid >> 5, lane = tid & 31;
    const int wm = wid & 1, wn = wid >> 1;
    const int bm = blockIdx.y * 128, bn = blockIdx.x * 128;
    const bf16* As[2] = {A0, A1};
    const bf16* Bs[2] = {B0, B1};

    uint32_t sb = (smem_u32(dsm) + 1023u) & ~1023u;
    const int nch = K >> 6;

    auto load_tile = [&](uint32_t st, const bf16* g, int ld, int c0){
#pragma unroll
        for (int t = 0; t < 4; t++){
            int c = tid + t * 256, r = c >> 3, c8 = c & 7;
            cp16(st + (uint32_t)(r * 128) + (uint32_t)(((c8 ^ (r & 7)) * 16)),
                 g + (size_t)r * ld + c0 + c8 * 8);
        }
    };
    auto load_chunk = [&](int stage, int k0){
        uint32_t st = sb + stage * 65536u;
#pragma unroll
        for (int sp = 0; sp < 2; sp++) load_tile(st + sp * 16384, As[sp] + (size_t)bm * lda, lda, k0);
#pragma unroll
        for (int sp = 0; sp < 2; sp++) load_tile(st + (2 + sp) * 16384, Bs[sp] + (size_t)bn * ldb, ldb, k0);
        cp_commit();
    };

    float acc[4][4][4];
#pragma unroll
    for (int i = 0; i < 4; i++)
#pragma unroll
        for (int j = 0; j < 4; j++)
#pragma unroll
            for (int u = 0; u < 4; u++) acc[i][j][u] = 0.0f;

    const int lr = lane & 15, lk = lane >> 4;

    load_chunk(0, 0);
    for (int c = 0; c < nch; c++){
        const int s = c & 1;
        if (c + 1 < nch){ load_chunk((c + 1) & 1, (c + 1) << 6); cp_wait<1>(); }
        else cp_wait<0>();
        __syncthreads();

        const uint32_t stg = sb + s * 65536u;
#pragma unroll
        for (int ks = 0; ks < 4; ks++){
            const int kc = ks * 2 + lk;
            uint32_t af[2][4][4], bfr[2][2][4];
#pragma unroll
            for (int sp = 0; sp < 2; sp++)
#pragma unroll
                for (int i = 0; i < 4; i++){
                    int r = wm * 64 + i * 16 + lr;
                    ldsm4(af[sp][i], stg + sp * 16384 + (uint32_t)(r * 128) + (uint32_t)(((kc ^ (r & 7)) * 16)));
                }
#pragma unroll
            for (int sp = 0; sp < 2; sp++)
#pragma unroll
                for (int j2 = 0; j2 < 2; j2++){
                    int rn = wn * 32 + j2 * 16 + lr;
                    ldsm4(bfr[sp][j2], stg + (2 + sp) * 16384 + (uint32_t)(rn * 128) + (uint32_t)(((kc ^ (rn & 7)) * 16)));
                }
#pragma unroll
            for (int i = 0; i < 4; i++)
#pragma unroll
                for (int j2 = 0; j2 < 2; j2++){
                    mma16816(acc[i][2*j2],   af[0][i], bfr[0][j2][0], bfr[0][j2][2]);
                    mma16816(acc[i][2*j2+1], af[0][i], bfr[0][j2][1], bfr[0][j2][3]);
                    mma16816(acc[i][2*j2],   af[0][i], bfr[1][j2][0], bfr[1][j2][2]);
                    mma16816(acc[i][2*j2+1], af[0][i], bfr[1][j2][1], bfr[1][j2][3]);
                    mma16816(acc[i][2*j2],   af[1][i], bfr[0][j2][0], bfr[0][j2][2]);
                    mma16816(acc[i][2*j2+1], af[1][i], bfr[0][j2][1], bfr[0][j2][3]);
                }
        }
        __syncthreads();
    }

    const int tr = lane >> 2, tc = (lane & 3) * 2;
#pragma unroll
    for (int i = 0; i < 4; i++)
#pragma unroll
        for (int h2 = 0; h2 < 2; h2++){
            const int row = bm + wm * 64 + i * 16 + tr + h2 * 8;
#pragma unroll
            for (int j = 0; j < 4; j++){
                const int col = bn + wn * 32 + j * 8 + tc;
                float v0 = acc[i][j][h2*2], v1 = acc[i][j][h2*2+1];
                if (bias){ v0 += bias[col]; v1 += bias[col+1]; }
                if (OUTMODE == 1){
                    v0 = v0 / (1.0f + expf(-v0));
                    v1 = v1 / (1.0f + expf(-v1));
                }
                *(float2*)(C + (size_t)row * ldc + col) = make_float2(v0, v1);
            }
        }
}

// ---------------- preprocessing ----------------
__global__ __launch_bounds__(256) void split3_kernel(const float2* __restrict__ in,
    bf16* __restrict__ h, bf16* __restrict__ m, bf16* __restrict__ l, int n2)
{
    int i = blockIdx.x * 256 + threadIdx.x;
    if (i >= n2) return;
    float2 v = in[i];
    bf16 h0,l0,h1,l1;
    split2v(v.x,h0,l0); split2v(v.y,h1,l1);
    ((uint32_t*)h)[i] = (uint32_t)__bfloat16_as_ushort(h0) | ((uint32_t)__bfloat16_as_ushort(h1) << 16);
    ((uint32_t*)m)[i] = (uint32_t)__bfloat16_as_ushort(l0) | ((uint32_t)__bfloat16_as_ushort(l1) << 16);
    (void)l;
}

// in: [K][N] row-major -> out 2 splits: [N][K]
__global__ void tsplit_kernel(const float* __restrict__ in,
    bf16* __restrict__ o0, bf16* __restrict__ o1, int K, int N)
{
    __shared__ float t[32][33];
    int k0 = blockIdx.y * 32, n0 = blockIdx.x * 32;
    t[threadIdx.y][threadIdx.x] = in[(size_t)(k0 + threadIdx.y) * N + n0 + threadIdx.x];
    __syncthreads();
    float v = t[threadIdx.x][threadIdx.y];
    size_t o = (size_t)(n0 + threadIdx.y) * K + k0 + threadIdx.x;
    bf16 h, l; split2v(v, h, l);
    o0[o] = h; o1[o] = l;
}

// ---------------- stage-1 top-32 of 512 per (n, ht)  [R0 verbatim] ----------------
__global__ __launch_bounds__(256) void topk1_kernel()
{
    int n = blockIdx.x;
    int w = threadIdx.x >> 5;
    int lane = threadIdx.x & 31;
    const float* sc = g_scores + (size_t)n * 4096 + (size_t)w * 512;

    __shared__ float sv[8][16][32];

    float lmax = -FLT_MAX; int lslot = 0;
#pragma unroll
    for (int i = 0; i < 16; i++){
        float v = sc[i * 32 + lane];
        sv[w][i][lane] = v;
        if (v > lmax){ lmax = v; lslot = i; }
    }
    __syncwarp();

    float outV = 0.0f; int outI = 0;
    const unsigned FULL = 0xffffffffu;
    for (int it = 0; it < 32; it++){
        float m = lmax;
        int mk = lslot * 32 + lane;
#pragma unroll
        for (int off = 16; off; off >>= 1){
            float om = __shfl_xor_sync(FULL, m, off);
            int   ok = __shfl_xor_sync(FULL, mk, off);
            if (om > m || (om == m && ok < mk)){ m = om; mk = ok; }
        }
        if (lane == it){ outV = m; outI = mk; }
        if (lane == (mk & 31)){
            sv[w][mk >> 5][lane] = -FLT_MAX;
            lmax = -FLT_MAX; lslot = 0;
#pragma unroll
            for (int i = 0; i < 16; i++){
                float v = sv[w][i][lane];
                if (v > lmax){ lmax = v; lslot = i; }
            }
        }
    }
    size_t o = ((size_t)n * 8 + w) * KNN_K + lane;
    g_ts[o] = outV;
    g_ti[o] = outI;
}

// ---------------- stage-2 all-pairs top-32 + softmax  [R0 verbatim] ----------------
__global__ __launch_bounds__(128) void topk2_kernel()
{
    int n = blockIdx.x;
    int h = threadIdx.x >> 5;
    int lane = threadIdx.x & 31;

    size_t base1 = ((size_t)n * 8 + h * 2) * KNN_K;
    size_t base2 = base1 + KNN_K;

    __shared__ float s2s[4][32];
    __shared__ int   i1s[4][32];
    __shared__ int   i2s[4][32];

    float s1 = g_ts[base1 + lane];
    s2s[h][lane] = g_ts[base2 + lane];
    i1s[h][lane] = g_ti[base1 + lane];
    i2s[h][lane] = g_ti[base2 + lane];
    __syncwarp();

    unsigned alive = 0xffffffffu;
    float rmax = -FLT_MAX; int rj = 0;
    for (int j = 0; j < 32; j++){
        float c = s1 + s2s[h][j];
        if (c > rmax){ rmax = c; rj = j; }
    }

    float outS = 0.0f; int outIdx = 0;
    const unsigned FULL = 0xffffffffu;
    for (int it = 0; it < 32; it++){
        float m = rmax;
        int mk = lane * 32 + rj;
#pragma unroll
        for (int off = 16; off; off >>= 1){
            float om = __shfl_xor_sync(FULL, m, off);
            int   ok = __shfl_xor_sync(FULL, mk, off);
            if (om > m || (om == m && ok < mk)){ m = om; mk = ok; }
        }
        if (lane == it){
            outS = m;
            outIdx = i1s[h][mk >> 5] * 512 + i2s[h][mk & 31];
        }
        if (lane == (mk >> 5)){
            alive &= ~(1u << (mk & 31));
            rmax = -FLT_MAX; rj = 0;
            for (int j = 0; j < 32; j++){
                if ((alive >> j) & 1u){
                    float c = s1 + s2s[h][j];
                    if (c > rmax){ rmax = c; rj = j; }
                }
            }
        }
    }

    float mx = __shfl_sync(FULL, outS, 0);
    float e = expf(outS - mx);
    float s = e;
#pragma unroll
    for (int off = 16; off; off >>= 1) s += __shfl_xor_sync(FULL, s, off);
    float wgt = e / s;

    size_t o = ((size_t)n * 4 + h) * KNN_K + lane;
    g_cw[o] = wgt;
    g_ci[o] = outIdx;
}

// ---------------- gather + gate + 2-way split ----------------
__global__ __launch_bounds__(128) void gather_kernel(const float* __restrict__ values)
{
    int n = blockIdx.x, t = threadIdx.x;
    __shared__ float sw[128]; __shared__ int sid[128];
    sw[t]  = g_cw[(size_t)n * 128 + t];
    sid[t] = g_ci[(size_t)n * 128 + t];
    __syncthreads();
    float4 acc = {0.f,0.f,0.f,0.f};
#pragma unroll 4
    for (int r = 0; r < 128; r++){
        float wr = sw[r];
        const float4 v = *((const float4*)(values + (size_t)sid[r] * 512) + t);
        acc.x += wr*v.x; acc.y += wr*v.y; acc.z += wr*v.z; acc.w += wr*v.w;
    }
    float4 g = *(const float4*)(g_gate + (size_t)n * 512 + t * 4);
    float o[4] = {acc.x*g.x, acc.y*g.y, acc.z*g.z, acc.w*g.w};
    uint32_t hp[2], lp[2];
#pragma unroll
    for (int u = 0; u < 2; u++){
        bf16 h0,l0,h1,l1;
        split2v(o[u*2],h0,l0); split2v(o[u*2+1],h1,l1);
        hp[u] = (uint32_t)__bfloat16_as_ushort(h0) | ((uint32_t)__bfloat16_as_ushort(h1) << 16);
        lp[u] = (uint32_t)__bfloat16_as_ushort(l0) | ((uint32_t)__bfloat16_as_ushort(l1) << 16);
    }
    *(uint2*)(&g_h2[0][(size_t)n * 512 + t * 4]) = make_uint2(hp[0], hp[1]);
    *(uint2*)(&g_h2[1][(size_t)n * 512 + t * 4]) = make_uint2(lp[0], lp[1]);
}

// ---------------- launch ----------------
extern "C" void kernel_launch(void* const* d_in, const int* in_sizes, int n_in,
                              void* d_out, int out_size)
{
    const float* x      = (const float*)d_in[0];
    const float* Wq     = (const float*)d_in[1];
    const float* bq     = (const float*)d_in[2];
    const float* keys   = (const float*)d_in[3];
    const float* values = (const float*)d_in[4];
    const float* Ws     = (const float*)d_in[5];
    const float* bs     = (const float*)d_in[6];
    const float* Wv     = (const float*)d_in[7];
    const float* bv     = (const float*)d_in[8];
    float* out          = (float*)d_out;

    const int SMEM2 = 2 * 2 * 32768;   // 128 KB double-buffered 2-split
    cudaFuncSetAttribute(gemm_mma<0>, cudaFuncAttributeMaxDynamicSharedMemorySize, SMEM2);
    cudaFuncSetAttribute(gemm_mma<1>, cudaFuncAttributeMaxDynamicSharedMemorySize, SMEM2);

    float *q, *scores, *gate;
    bf16 *x3[2], *ws2[2], *wv2[2], *h2[2];
    cudaGetSymbolAddress((void**)&q, g_q);
    cudaGetSymbolAddress((void**)&scores, g_scores);
    cudaGetSymbolAddress((void**)&gate, g_gate);
    {
        bf16* base;
        cudaGetSymbolAddress((void**)&base, g_x3);  for (int i=0;i<2;i++) x3[i]  = base + (size_t)i*2048*1024;
        cudaGetSymbolAddress((void**)&base, g_ws2); for (int i=0;i<2;i++) ws2[i] = base + (size_t)i*512*1024;
        cudaGetSymbolAddress((void**)&base, g_wv2); for (int i=0;i<2;i++) wv2[i] = base + (size_t)i*1024*512;
        cudaGetSymbolAddress((void**)&base, g_h2);  for (int i=0;i<2;i++) h2[i]  = base + (size_t)i*2048*512;
    }

    // preprocessing for HMMA smooth paths
    split3_kernel<<<4096, 256>>>((const float2*)x, x3[0], x3[1], nullptr, 2048*1024/2);
    tsplit_kernel<<<dim3(16, 32), dim3(32, 32)>>>(Ws, ws2[0], ws2[1], 1024, 512);
    tsplit_kernel<<<dim3(32, 16), dim3(32, 32)>>>(Wv, wv2[0], wv2[1], 512, 1024);

    // 1) q = x @ Wq + bq  (fp32, f32x2-packed, R0-identical numerics)
    gemm_f2<false><<<dim3(2048/64, 2048/128, 1), 256>>>(
        x, Wq, bq, q, 1024, 1024, 2048, 2048, 0, 0, 0);

    // 2) scores = q @ keys^T  (8 batches, fp32 f32x2)
    gemm_f2<true><<<dim3(512/64, 2048/128, 8), 256>>>(
        q, keys, nullptr, scores, 256, 2048, 256, 4096, 256L, 512L*256L, 512L);

    // 3) stage-1 top-32   4) stage-2 + softmax   (R0 verbatim)
    topk1_kernel<<<2048, 256>>>();
    topk2_kernel<<<2048, 128>>>();

    // 5) gate = silu(x @ Ws + bs)  (HMMA 2-split, smooth)
    gemm_mma<1><<<dim3(4,16,1), 256, SMEM2>>>(
        x3[0], x3[1], ws2[0], ws2[1], bs, gate, 1024, 1024, 1024, 512);

    // 6) hidden = gate * gathered values -> 2-way bf16 split
    gather_kernel<<<2048, 128>>>(values);

    // 7) out = hidden @ Wv + bv  (HMMA 2-split, smooth)
    gemm_mma<0><<<dim3(8,16,1), 256, SMEM2>>>(
        h2[0], h2[1], wv2[0], wv2[1], bv, out, 512, 512, 512, 1024);
}

// round 7
// speedup vs baseline: 1.5031x; 1.5031x over previous
#include <cuda_runtime.h>
#include <cuda_bf16.h>
#include <math.h>
#include <float.h>
#include <string.h>
#include <stdint.h>

#define KNN_K 32
typedef __nv_bfloat16 bf16;

// ---------------- scratch ----------------
__device__ __align__(16) float g_q[2048*2048];
__device__ __align__(16) float g_scores[2048*4096];
__device__ __align__(16) bf16 g_x2[2][2048*1024];
__device__ __align__(16) bf16 g_ws2[2][512*1024];
__device__ __align__(16) bf16 g_wv2[2][1024*512];
__device__ __align__(16) bf16 g_h2[2][2048*512];
__device__ __align__(16) float g_ts[2048*8*32];
__device__ int   g_ti[2048*8*32];
__device__ __align__(16) float g_cw[2048*4*32];
__device__ int   g_ci[2048*4*32];
__device__ __align__(16) float g_gate[2048*512];

// ---------------- helpers ----------------
__device__ __forceinline__ uint32_t smem_u32(const void* p){ return (uint32_t)__cvta_generic_to_shared(p); }
__device__ __forceinline__ void cp16(uint32_t dst, const void* src){
    asm volatile("cp.async.cg.shared.global [%0], [%1], 16;\n" :: "r"(dst), "l"(src));
}
__device__ __forceinline__ void cp_commit(){ asm volatile("cp.async.commit_group;\n" ::: "memory"); }
template<int N> __device__ __forceinline__ void cp_wait(){ asm volatile("cp.async.wait_group %0;\n" :: "n"(N) : "memory"); }
__device__ __forceinline__ void ldsm4(uint32_t (&r)[4], uint32_t addr){
    asm volatile("ldmatrix.sync.aligned.m8n8.x4.shared.b16 {%0,%1,%2,%3}, [%4];"
        : "=r"(r[0]), "=r"(r[1]), "=r"(r[2]), "=r"(r[3]) : "r"(addr));
}
__device__ __forceinline__ void mma16816(float (&d)[4], const uint32_t (&a)[4], uint32_t b0, uint32_t b1){
    asm volatile("mma.sync.aligned.m16n8k16.row.col.f32.bf16.bf16.f32 "
        "{%0,%1,%2,%3}, {%4,%5,%6,%7}, {%8,%9}, {%0,%1,%2,%3};"
        : "+f"(d[0]), "+f"(d[1]), "+f"(d[2]), "+f"(d[3])
        : "r"(a[0]), "r"(a[1]), "r"(a[2]), "r"(a[3]), "r"(b0), "r"(b1));
}
__device__ __forceinline__ void ffma2(uint64_t& d, uint64_t a, uint64_t b){
    asm("fma.rn.f32x2 %0, %1, %2, %3;" : "=l"(d) : "l"(a), "l"(b), "l"(d));
}
__device__ __forceinline__ uint64_t pack2(float v){
    uint64_t d; asm("mov.b64 %0, {%1, %1};" : "=l"(d) : "f"(v)); return d;
}
__device__ __forceinline__ void split2v(float v, bf16& h, bf16& l){
    h = __float2bfloat16(v);
    l = __float2bfloat16(v - __bfloat162float(h));
}

// ---------------- fp32 GEMM via f32x2, reg-packed B (bitwise == scalar fp32) ----------------
// C = A @ B (+bias); BT: B is [N][K] row-major -> C = A @ B^T
template<bool BT>
__global__ __launch_bounds__(256) void gemm_f2(
    const float* __restrict__ A, const float* __restrict__ B,
    const float* __restrict__ bias, float* __restrict__ C,
    int K, int lda, int ldb, int ldc, long sA, long sB, long sC)
{
    constexpr int BM = 128, BN = 64, BK = 16;
    __shared__ float As[BK][BM];
    __shared__ float Bs[BK][BN];

    A += (long)blockIdx.z * sA;
    B += (long)blockIdx.z * sB;
    C += (long)blockIdx.z * sC;

    const int bm = blockIdx.y * BM, bn = blockIdx.x * BN;
    const int tid = threadIdx.x;
    const int tx = tid & 15;   // 4 cols:  tx*4
    const int ty = tid >> 4;   // 8 rows:  ty*8

    uint64_t acc2[4][4];
#pragma unroll
    for (int i = 0; i < 4; i++)
#pragma unroll
        for (int j = 0; j < 4; j++) acc2[i][j] = 0ull;

    // register-prefetch double buffering
    const int ar = tid >> 2, ac = (tid & 3) * 4;     // A: rows ar, ar+64; cols ac..ac+3
    float4 ra0, ra1, rb;
    auto ldg = [&](int k0){
        ra0 = *(const float4*)(A + (long)(bm + ar) * lda + k0 + ac);
        ra1 = *(const float4*)(A + (long)(bm + ar + 64) * lda + k0 + ac);
        if (BT) rb = *(const float4*)(B + (long)(bn + ar) * ldb + k0 + ac);
        else    rb = *(const float4*)(B + (long)(k0 + (tid >> 4)) * ldb + bn + (tid & 15) * 4);
    };
    auto sts = [&](){
        As[ac + 0][ar] = ra0.x; As[ac + 1][ar] = ra0.y;
        As[ac + 2][ar] = ra0.z; As[ac + 3][ar] = ra0.w;
        As[ac + 0][ar + 64] = ra1.x; As[ac + 1][ar + 64] = ra1.y;
        As[ac + 2][ar + 64] = ra1.z; As[ac + 3][ar + 64] = ra1.w;
        if (BT){
            Bs[ac + 0][ar] = rb.x; Bs[ac + 1][ar] = rb.y;
            Bs[ac + 2][ar] = rb.z; Bs[ac + 3][ar] = rb.w;
        } else {
            *(float4*)&Bs[tid >> 4][(tid & 15) * 4] = rb;
        }
    };

    const int nch = K / BK;
    ldg(0);
    for (int c = 0; c < nch; c++){
        sts();
        __syncthreads();
        if (c + 1 < nch) ldg((c + 1) * BK);     // overlap with compute

#pragma unroll
        for (int kk = 0; kk < BK; kk++){
            uint64_t a2[4];
            *(uint4*)&a2[0] = *(const uint4*)&As[kk][ty * 8];       // row pairs {0,1},{2,3}
            *(uint4*)&a2[2] = *(const uint4*)&As[kk][ty * 8 + 4];   // {4,5},{6,7}
            float4 b4 = *(const float4*)&Bs[kk][tx * 4];
            uint64_t b2[4] = {pack2(b4.x), pack2(b4.y), pack2(b4.z), pack2(b4.w)};
#pragma unroll
            for (int i = 0; i < 4; i++)
#pragma unroll
                for (int j = 0; j < 4; j++)
                    ffma2(acc2[i][j], a2[i], b2[j]);
        }
        __syncthreads();
    }

#pragma unroll
    for (int i2 = 0; i2 < 4; i2++){
#pragma unroll
        for (int j = 0; j < 4; j++){
            float2 p; memcpy(&p, &acc2[i2][j], 8);
            int col = bn + tx * 4 + j;
            float b = bias ? bias[col] : 0.0f;
            int r0 = bm + ty * 8 + i2 * 2;
            C[(long)r0 * ldc + col]       = p.x + b;
            C[(long)(r0 + 1) * ldc + col] = p.y + b;
        }
    }
}

// ---------------- HMMA 2-split GEMM (smooth paths): C = A @ B^T ----------------
template<int OUTMODE>   // 0 = fp32+bias, 1 = fp32 silu+bias
__global__ __launch_bounds__(256, 1) void gemm_mma(
    const bf16* __restrict__ A0, const bf16* __restrict__ A1,
    const bf16* __restrict__ B0, const bf16* __restrict__ B1,
    const float* __restrict__ bias, float* __restrict__ C,
    int K, int lda, int ldb, int ldc)
{
    extern __shared__ char dsm[];
    const int tid = threadIdx.x, wid = tid >> 5, lane = tid & 31;
    const int wm = wid & 1, wn = wid >> 1;
    const int bm = blockIdx.y * 128, bn = blockIdx.x * 128;
    const bf16* As[2] = {A0, A1};
    const bf16* Bs[2] = {B0, B1};

    uint32_t sb = (smem_u32(dsm) + 1023u) & ~1023u;
    const int nch = K >> 6;

    auto load_tile = [&](uint32_t st, const bf16* g, int ld, int c0){
#pragma unroll
        for (int t = 0; t < 4; t++){
            int c = tid + t * 256, r = c >> 3, c8 = c & 7;
            cp16(st + (uint32_t)(r * 128) + (uint32_t)(((c8 ^ (r & 7)) * 16)),
                 g + (size_t)r * ld + c0 + c8 * 8);
        }
    };
    auto load_chunk = [&](int stage, int k0){
        uint32_t st = sb + stage * 65536u;
#pragma unroll
        for (int sp = 0; sp < 2; sp++) load_tile(st + sp * 16384, As[sp] + (size_t)bm * lda, lda, k0);
#pragma unroll
        for (int sp = 0; sp < 2; sp++) load_tile(st + (2 + sp) * 16384, Bs[sp] + (size_t)bn * ldb, ldb, k0);
        cp_commit();
    };

    float acc[4][4][4];
#pragma unroll
    for (int i = 0; i < 4; i++)
#pragma unroll
        for (int j = 0; j < 4; j++)
#pragma unroll
            for (int u = 0; u < 4; u++) acc[i][j][u] = 0.0f;

    const int lr = lane & 15, lk = lane >> 4;

    load_chunk(0, 0);
    for (int c = 0; c < nch; c++){
        const int s = c & 1;
        if (c + 1 < nch){ load_chunk((c + 1) & 1, (c + 1) << 6); cp_wait<1>(); }
        else cp_wait<0>();
        __syncthreads();

        const uint32_t stg = sb + s * 65536u;
#pragma unroll
        for (int ks = 0; ks < 4; ks++){
            const int kc = ks * 2 + lk;
            uint32_t af[2][4][4], bfr[2][2][4];
#pragma unroll
            for (int sp = 0; sp < 2; sp++)
#pragma unroll
                for (int i = 0; i < 4; i++){
                    int r = wm * 64 + i * 16 + lr;
                    ldsm4(af[sp][i], stg + sp * 16384 + (uint32_t)(r * 128) + (uint32_t)(((kc ^ (r & 7)) * 16)));
                }
#pragma unroll
            for (int sp = 0; sp < 2; sp++)
#pragma unroll
                for (int j2 = 0; j2 < 2; j2++){
                    int rn = wn * 32 + j2 * 16 + lr;
                    ldsm4(bfr[sp][j2], stg + (2 + sp) * 16384 + (uint32_t)(rn * 128) + (uint32_t)(((kc ^ (rn & 7)) * 16)));
                }
#pragma unroll
            for (int i = 0; i < 4; i++)
#pragma unroll
                for (int j2 = 0; j2 < 2; j2++){
                    mma16816(acc[i][2*j2],   af[0][i], bfr[0][j2][0], bfr[0][j2][2]);
                    mma16816(acc[i][2*j2+1], af[0][i], bfr[0][j2][1], bfr[0][j2][3]);
                    mma16816(acc[i][2*j2],   af[0][i], bfr[1][j2][0], bfr[1][j2][2]);
                    mma16816(acc[i][2*j2+1], af[0][i], bfr[1][j2][1], bfr[1][j2][3]);
                    mma16816(acc[i][2*j2],   af[1][i], bfr[0][j2][0], bfr[0][j2][2]);
                    mma16816(acc[i][2*j2+1], af[1][i], bfr[0][j2][1], bfr[0][j2][3]);
                }
        }
        __syncthreads();
    }

    const int tr = lane >> 2, tc = (lane & 3) * 2;
#pragma unroll
    for (int i = 0; i < 4; i++)
#pragma unroll
        for (int h2 = 0; h2 < 2; h2++){
            const int row = bm + wm * 64 + i * 16 + tr + h2 * 8;
#pragma unroll
            for (int j = 0; j < 4; j++){
                const int col = bn + wn * 32 + j * 8 + tc;
                float v0 = acc[i][j][h2*2], v1 = acc[i][j][h2*2+1];
                if (bias){ v0 += bias[col]; v1 += bias[col+1]; }
                if (OUTMODE == 1){
                    v0 = v0 / (1.0f + expf(-v0));
                    v1 = v1 / (1.0f + expf(-v1));
                }
                *(float2*)(C + (size_t)row * ldc + col) = make_float2(v0, v1);
            }
        }
}

// ---------------- preprocessing ----------------
__global__ __launch_bounds__(256) void split2_kernel(const float2* __restrict__ in,
    bf16* __restrict__ h, bf16* __restrict__ l, int n2)
{
    int i = blockIdx.x * 256 + threadIdx.x;
    if (i >= n2) return;
    float2 v = in[i];
    bf16 h0,l0,h1,l1;
    split2v(v.x,h0,l0); split2v(v.y,h1,l1);
    ((uint32_t*)h)[i] = (uint32_t)__bfloat16_as_ushort(h0) | ((uint32_t)__bfloat16_as_ushort(h1) << 16);
    ((uint32_t*)l)[i] = (uint32_t)__bfloat16_as_ushort(l0) | ((uint32_t)__bfloat16_as_ushort(l1) << 16);
}

__global__ void tsplit_kernel(const float* __restrict__ in,
    bf16* __restrict__ o0, bf16* __restrict__ o1, int K, int N)
{
    __shared__ float t[32][33];
    int k0 = blockIdx.y * 32, n0 = blockIdx.x * 32;
    t[threadIdx.y][threadIdx.x] = in[(size_t)(k0 + threadIdx.y) * N + n0 + threadIdx.x];
    __syncthreads();
    float v = t[threadIdx.x][threadIdx.y];
    size_t o = (size_t)(n0 + threadIdx.y) * K + k0 + threadIdx.x;
    bf16 h, l; split2v(v, h, l);
    o0[o] = h; o1[o] = l;
}

// ---------------- stage-1 top-32 of 512 per (n, ht): register rescan ----------------
__global__ __launch_bounds__(256) void topk1_kernel()
{
    int n = blockIdx.x, w = threadIdx.x >> 5, lane = threadIdx.x & 31;
    const float* sc = g_scores + (size_t)n * 4096 + (size_t)w * 512;
    float v[16]; float lmax = -FLT_MAX; int lslot = 0;
#pragma unroll
    for (int i = 0; i < 16; i++){
        v[i] = sc[i * 32 + lane];
        if (v[i] > lmax){ lmax = v[i]; lslot = i; }
    }
    float outV = 0.0f; int outI = 0;
    const unsigned FULL = 0xffffffffu;
    for (int it = 0; it < 32; it++){
        float m = lmax; int mk = lslot * 32 + lane;
#pragma unroll
        for (int off = 16; off; off >>= 1){
            float om = __shfl_xor_sync(FULL, m, off);
            int   ok = __shfl_xor_sync(FULL, mk, off);
            if (om > m || (om == m && ok < mk)){ m = om; mk = ok; }
        }
        if (lane == it){ outV = m; outI = mk; }
        if ((mk & 31) == lane){
            int ds = mk >> 5;
#pragma unroll
            for (int i = 0; i < 16; i++) if (i == ds) v[i] = -FLT_MAX;
            lmax = -FLT_MAX; lslot = 0;
#pragma unroll
            for (int i = 0; i < 16; i++) if (v[i] > lmax){ lmax = v[i]; lslot = i; }
        }
    }
    size_t o = ((size_t)n * 8 + w) * KNN_K + lane;
    g_ts[o] = outV; g_ti[o] = outI;
}

// ---------------- stage-2: dominance pruning + counting selection (exact) ----------------
// pair (i,j) in top-32 => (i+1)*(j+1) <= 32 : 119 candidates (+9 pad)
__constant__ unsigned short c_cand[128] = {
    0x000,0x001,0x002,0x003,0x004,0x005,0x006,0x007,0x008,0x009,0x00A,0x00B,0x00C,0x00D,0x00E,0x00F,
    0x010,0x011,0x012,0x013,0x014,0x015,0x016,0x017,0x018,0x019,0x01A,0x01B,0x01C,0x01D,0x01E,0x01F,
    0x100,0x101,0x102,0x103,0x104,0x105,0x106,0x107,0x108,0x109,0x10A,0x10B,0x10C,0x10D,0x10E,0x10F,
    0x200,0x201,0x202,0x203,0x204,0x205,0x206,0x207,0x208,0x209,
    0x300,0x301,0x302,0x303,0x304,0x305,0x306,0x307,
    0x400,0x401,0x402,0x403,0x404,0x405,
    0x500,0x501,0x502,0x503,0x504,
    0x600,0x601,0x602,0x603,
    0x700,0x701,0x702,0x703,
    0x800,0x801,0x802, 0x900,0x901,0x902,
    0xA00,0xA01, 0xB00,0xB01, 0xC00,0xC01, 0xD00,0xD01, 0xE00,0xE01, 0xF00,0xF01,
    0x1000,0x1100,0x1200,0x1300,0x1400,0x1500,0x1600,0x1700,
    0x1800,0x1900,0x1A00,0x1B00,0x1C00,0x1D00,0x1E00,0x1F00,
    0xFFFF,0xFFFF,0xFFFF,0xFFFF,0xFFFF,0xFFFF,0xFFFF,0xFFFF,0xFFFF };

__global__ __launch_bounds__(128) void topk2_kernel()
{
    int n = blockIdx.x, h = threadIdx.x >> 5, lane = threadIdx.x & 31;
    const unsigned FULL = 0xffffffffu;
    __shared__ unsigned long long skeys[4][128];
    __shared__ int si1[4][32], si2[4][32];

    size_t b1 = ((size_t)n * 8 + h * 2) * KNN_K;
    float s1 = g_ts[b1 + lane];
    float s2 = g_ts[b1 + KNN_K + lane];
    si1[h][lane] = g_ti[b1 + lane];
    si2[h][lane] = g_ti[b1 + KNN_K + lane];
    __syncwarp();

    float val[4]; unsigned long long key[4]; int ci_[4], cj_[4]; bool real[4];
#pragma unroll
    for (int s = 0; s < 4; s++){
        unsigned pk = c_cand[lane * 4 + s];
        int ci = (pk >> 8) & 31, cj = pk & 31;
        ci_[s] = ci; cj_[s] = cj;
        real[s] = (pk != 0xFFFFu);
        float v = __shfl_sync(FULL, s1, ci) + __shfl_sync(FULL, s2, cj);
        val[s] = v;
        unsigned u = __float_as_uint(v);
        unsigned sv = (u & 0x80000000u) ? ~u : (u | 0x80000000u);
        unsigned p = (unsigned)(ci * 32 + cj);
        key[s] = real[s] ? (((unsigned long long)sv << 32) | (unsigned long long)(1023u - p)) : 0ull;
        skeys[h][lane * 4 + s] = key[s];
    }
    __syncwarp();

    int cnt[4] = {0,0,0,0};
    for (int k2 = 0; k2 < 128; k2++){
        unsigned long long o = skeys[h][k2];
#pragma unroll
        for (int s = 0; s < 4; s++) cnt[s] += (o > key[s]);
    }
    bool sel[4];
#pragma unroll
    for (int s = 0; s < 4; s++) sel[s] = real[s] && (cnt[s] < 32);

    float m = -FLT_MAX;
#pragma unroll
    for (int s = 0; s < 4; s++) if (sel[s] && val[s] > m) m = val[s];
#pragma unroll
    for (int off = 16; off; off >>= 1) m = fmaxf(m, __shfl_xor_sync(FULL, m, off));
    float e[4], sum = 0.0f;
#pragma unroll
    for (int s = 0; s < 4; s++){ e[s] = sel[s] ? expf(val[s] - m) : 0.0f; sum += e[s]; }
#pragma unroll
    for (int off = 16; off; off >>= 1) sum += __shfl_xor_sync(FULL, sum, off);

    size_t ob = ((size_t)n * 4 + h) * KNN_K;
#pragma unroll
    for (int s = 0; s < 4; s++){
        if (sel[s]){
            g_cw[ob + cnt[s]] = e[s] / sum;      // deterministic rank slot
            g_ci[ob + cnt[s]] = si1[h][ci_[s]] * 512 + si2[h][cj_[s]];
        }
    }
}

// ---------------- gather + gate + 2-way split ----------------
__global__ __launch_bounds__(128) void gather_kernel(const float* __restrict__ values)
{
    int n = blockIdx.x, t = threadIdx.x;
    __shared__ float sw[128]; __shared__ int sid[128];
    sw[t]  = g_cw[(size_t)n * 128 + t];
    sid[t] = g_ci[(size_t)n * 128 + t];
    __syncthreads();
    float4 acc = {0.f,0.f,0.f,0.f};
#pragma unroll 4
    for (int r = 0; r < 128; r++){
        float wr = sw[r];
        const float4 v = *((const float4*)(values + (size_t)sid[r] * 512) + t);
        acc.x += wr*v.x; acc.y += wr*v.y; acc.z += wr*v.z; acc.w += wr*v.w;
    }
    float4 g = *(const float4*)(g_gate + (size_t)n * 512 + t * 4);
    float o[4] = {acc.x*g.x, acc.y*g.y, acc.z*g.z, acc.w*g.w};
    uint32_t hp[2], lp[2];
#pragma unroll
    for (int u = 0; u < 2; u++){
        bf16 h0,l0,h1,l1;
        split2v(o[u*2],h0,l0); split2v(o[u*2+1],h1,l1);
        hp[u] = (uint32_t)__bfloat16_as_ushort(h0) | ((uint32_t)__bfloat16_as_ushort(h1) << 16);
        lp[u] = (uint32_t)__bfloat16_as_ushort(l0) | ((uint32_t)__bfloat16_as_ushort(l1) << 16);
    }
    *(uint2*)(&g_h2[0][(size_t)n * 512 + t * 4]) = make_uint2(hp[0], hp[1]);
    *(uint2*)(&g_h2[1][(size_t)n * 512 + t * 4]) = make_uint2(lp[0], lp[1]);
}

// ---------------- launch ----------------
extern "C" void kernel_launch(void* const* d_in, const int* in_sizes, int n_in,
                              void* d_out, int out_size)
{
    const float* x      = (const float*)d_in[0];
    const float* Wq     = (const float*)d_in[1];
    const float* bq     = (const float*)d_in[2];
    const float* keys   = (const float*)d_in[3];
    const float* values = (const float*)d_in[4];
    const float* Ws     = (const float*)d_in[5];
    const float* bs     = (const float*)d_in[6];
    const float* Wv     = (const float*)d_in[7];
    const float* bv     = (const float*)d_in[8];
    float* out          = (float*)d_out;

    const int SMEM2 = 2 * 2 * 32768;
    cudaFuncSetAttribute(gemm_mma<0>, cudaFuncAttributeMaxDynamicSharedMemorySize, SMEM2);
    cudaFuncSetAttribute(gemm_mma<1>, cudaFuncAttributeMaxDynamicSharedMemorySize, SMEM2);

    float *q, *scores, *gate;
    bf16 *x2[2], *ws2[2], *wv2[2], *h2[2];
    cudaGetSymbolAddress((void**)&q, g_q);
    cudaGetSymbolAddress((void**)&scores, g_scores);
    cudaGetSymbolAddress((void**)&gate, g_gate);
    {
        bf16* base;
        cudaGetSymbolAddress((void**)&base, g_x2);  for (int i=0;i<2;i++) x2[i]  = base + (size_t)i*2048*1024;
        cudaGetSymbolAddress((void**)&base, g_ws2); for (int i=0;i<2;i++) ws2[i] = base + (size_t)i*512*1024;
        cudaGetSymbolAddress((void**)&base, g_wv2); for (int i=0;i<2;i++) wv2[i] = base + (size_t)i*1024*512;
        cudaGetSymbolAddress((void**)&base, g_h2);  for (int i=0;i<2;i++) h2[i]  = base + (size_t)i*2048*512;
    }

    // preprocessing for HMMA smooth paths
    split2_kernel<<<4096, 256>>>((const float2*)x, x2[0], x2[1], 2048*1024/2);
    tsplit_kernel<<<dim3(16, 32), dim3(32, 32)>>>(Ws, ws2[0], ws2[1], 1024, 512);
    tsplit_kernel<<<dim3(32, 16), dim3(32, 32)>>>(Wv, wv2[0], wv2[1], 512, 1024);

    // 1) q = x @ Wq + bq  (fp32, f32x2, exact)
    gemm_f2<false><<<dim3(2048/64, 2048/128, 1), 256>>>(
        x, Wq, bq, q, 1024, 1024, 2048, 2048, 0, 0, 0);

    // 2) scores = q @ keys^T  (8 batches, fp32 f32x2, exact)
    gemm_f2<true><<<dim3(512/64, 2048/128, 8), 256>>>(
        q, keys, nullptr, scores, 256, 2048, 256, 4096, 256L, 512L*256L, 512L);

    // 3) stage-1 top-32   4) stage-2 + softmax
    topk1_kernel<<<2048, 256>>>();
    topk2_kernel<<<2048, 128>>>();

    // 5) gate = silu(x @ Ws + bs)  (HMMA 2-split)
    gemm_mma<1><<<dim3(4,16,1), 256, SMEM2>>>(
        x2[0], x2[1], ws2[0], ws2[1], bs, gate, 1024, 1024, 1024, 512);

    // 6) hidden = gate * gathered values
    gather_kernel<<<2048, 128>>>(values);

    // 7) out = hidden @ Wv + bv  (HMMA 2-split)
    gemm_mma<0><<<dim3(8,16,1), 256, SMEM2>>>(
        h2[0], h2[1], wv2[0], wv2[1], bv, out, 512, 512, 512, 1024);
}

// round 8
// speedup vs baseline: 1.5124x; 1.0062x over previous
#include <cuda_runtime.h>
#include <cuda_bf16.h>
#include <math.h>
#include <float.h>
#include <string.h>
#include <stdint.h>

#define KNN_K 32
typedef __nv_bfloat16 bf16;

// ---------------- scratch ----------------
__device__ __align__(16) float g_q[2048*2048];
__device__ __align__(16) float g_scores[2048*4096];
__device__ __align__(16) bf16 g_x2[2][2048*1024];
__device__ __align__(16) bf16 g_ws2[2][512*1024];
__device__ __align__(16) bf16 g_wv2[2][1024*512];
__device__ __align__(16) bf16 g_h2[2][2048*512];
__device__ __align__(16) float g_ts[2048*8*32];
__device__ int   g_ti[2048*8*32];
__device__ __align__(16) float g_cw[2048*4*32];
__device__ int   g_ci[2048*4*32];
__device__ __align__(16) float g_gate[2048*512];

// ---------------- helpers ----------------
__device__ __forceinline__ uint32_t smem_u32(const void* p){ return (uint32_t)__cvta_generic_to_shared(p); }
__device__ __forceinline__ void cp16(uint32_t dst, const void* src){
    asm volatile("cp.async.cg.shared.global [%0], [%1], 16;\n" :: "r"(dst), "l"(src));
}
__device__ __forceinline__ void cp_commit(){ asm volatile("cp.async.commit_group;\n" ::: "memory"); }
template<int N> __device__ __forceinline__ void cp_wait(){ asm volatile("cp.async.wait_group %0;\n" :: "n"(N) : "memory"); }
__device__ __forceinline__ void ldsm4(uint32_t (&r)[4], uint32_t addr){
    asm volatile("ldmatrix.sync.aligned.m8n8.x4.shared.b16 {%0,%1,%2,%3}, [%4];"
        : "=r"(r[0]), "=r"(r[1]), "=r"(r[2]), "=r"(r[3]) : "r"(addr));
}
__device__ __forceinline__ void mma16816(float (&d)[4], const uint32_t (&a)[4], uint32_t b0, uint32_t b1){
    asm volatile("mma.sync.aligned.m16n8k16.row.col.f32.bf16.bf16.f32 "
        "{%0,%1,%2,%3}, {%4,%5,%6,%7}, {%8,%9}, {%0,%1,%2,%3};"
        : "+f"(d[0]), "+f"(d[1]), "+f"(d[2]), "+f"(d[3])
        : "r"(a[0]), "r"(a[1]), "r"(a[2]), "r"(a[3]), "r"(b0), "r"(b1));
}
__device__ __forceinline__ void ffma2(uint64_t& d, uint64_t a, uint64_t b){
    asm("fma.rn.f32x2 %0, %1, %2, %3;" : "=l"(d) : "l"(a), "l"(b), "l"(d));
}
__device__ __forceinline__ uint64_t pack2(float v){
    uint64_t d; asm("mov.b64 %0, {%1, %1};" : "=l"(d) : "f"(v)); return d;
}
__device__ __forceinline__ void split2v(float v, bf16& h, bf16& l){
    h = __float2bfloat16(v);
    l = __float2bfloat16(v - __bfloat162float(h));
}

// ---------------- fp32 GEMM via f32x2, 128x128 tile, 8x8/thread (exact fp32 chains) ----
// C = A @ B (+bias); BT: B is [N][K] row-major -> C = A @ B^T
template<bool BT>
__global__ __launch_bounds__(256) void gemm_f2(
    const float* __restrict__ A, const float* __restrict__ B,
    const float* __restrict__ bias, float* __restrict__ C,
    int K, int lda, int ldb, int ldc, long sA, long sB, long sC)
{
    constexpr int BM = 128, BN = 128, BK = 16;
    __shared__ float As[BK][BM];
    __shared__ float Bs[BK][BN];

    A += (long)blockIdx.z * sA;
    B += (long)blockIdx.z * sB;
    C += (long)blockIdx.z * sC;

    const int bm = blockIdx.y * BM, bn = blockIdx.x * BN;
    const int tid = threadIdx.x;
    const int tx = tid & 15;   // col groups: tx*4 and 64+tx*4
    const int ty = tid >> 4;   // rows: ty*8 .. +7

    uint64_t acc2[4][8];       // [row-pair][col]  rows {2i,2i+1}, cols j<4: tx*4+j, j>=4: 64+tx*4+j-4
#pragma unroll
    for (int i = 0; i < 4; i++)
#pragma unroll
        for (int j = 0; j < 8; j++) acc2[i][j] = 0ull;

    // register-prefetch double buffering
    const int ar = tid >> 2, ac = (tid & 3) * 4;
    float4 ra0, ra1, rb0, rb1;
    auto ldg = [&](int k0){
        ra0 = *(const float4*)(A + (long)(bm + ar) * lda + k0 + ac);
        ra1 = *(const float4*)(A + (long)(bm + ar + 64) * lda + k0 + ac);
        if (BT){
            rb0 = *(const float4*)(B + (long)(bn + ar) * ldb + k0 + ac);
            rb1 = *(const float4*)(B + (long)(bn + ar + 64) * ldb + k0 + ac);
        } else {
            rb0 = *(const float4*)(B + (long)(k0 + (tid >> 5)) * ldb + bn + (tid & 31) * 4);
            rb1 = *(const float4*)(B + (long)(k0 + (tid >> 5) + 8) * ldb + bn + (tid & 31) * 4);
        }
    };
    auto sts = [&](){
        As[ac + 0][ar] = ra0.x; As[ac + 1][ar] = ra0.y;
        As[ac + 2][ar] = ra0.z; As[ac + 3][ar] = ra0.w;
        As[ac + 0][ar + 64] = ra1.x; As[ac + 1][ar + 64] = ra1.y;
        As[ac + 2][ar + 64] = ra1.z; As[ac + 3][ar + 64] = ra1.w;
        if (BT){
            Bs[ac + 0][ar] = rb0.x; Bs[ac + 1][ar] = rb0.y;
            Bs[ac + 2][ar] = rb0.z; Bs[ac + 3][ar] = rb0.w;
            Bs[ac + 0][ar + 64] = rb1.x; Bs[ac + 1][ar + 64] = rb1.y;
            Bs[ac + 2][ar + 64] = rb1.z; Bs[ac + 3][ar + 64] = rb1.w;
        } else {
            *(float4*)&Bs[tid >> 5][(tid & 31) * 4]       = rb0;
            *(float4*)&Bs[(tid >> 5) + 8][(tid & 31) * 4] = rb1;
        }
    };

    const int nch = K / BK;
    ldg(0);
    for (int c = 0; c < nch; c++){
        sts();
        __syncthreads();
        if (c + 1 < nch) ldg((c + 1) * BK);

#pragma unroll
        for (int kk = 0; kk < BK; kk++){
            uint64_t a2[4];
            *(uint4*)&a2[0] = *(const uint4*)&As[kk][ty * 8];
            *(uint4*)&a2[2] = *(const uint4*)&As[kk][ty * 8 + 4];
            float4 b40 = *(const float4*)&Bs[kk][tx * 4];
            float4 b41 = *(const float4*)&Bs[kk][64 + tx * 4];
            uint64_t b2[8] = {pack2(b40.x), pack2(b40.y), pack2(b40.z), pack2(b40.w),
                              pack2(b41.x), pack2(b41.y), pack2(b41.z), pack2(b41.w)};
#pragma unroll
            for (int i = 0; i < 4; i++)
#pragma unroll
                for (int j = 0; j < 8; j++)
                    ffma2(acc2[i][j], a2[i], b2[j]);
        }
        __syncthreads();
    }

    // epilogue: two float4 stores per row (col groups tx*4 and 64+tx*4)
#pragma unroll
    for (int i = 0; i < 4; i++){
#pragma unroll
        for (int h2 = 0; h2 < 2; h2++){        // h2: low/high element of the f32x2 pair
            const int r = bm + ty * 8 + i * 2 + h2;
#pragma unroll
            for (int grp = 0; grp < 2; grp++){
                const int col = bn + grp * 64 + tx * 4;
                float4 o;
                float* po = &o.x;
#pragma unroll
                for (int u = 0; u < 4; u++){
                    float2 p; memcpy(&p, &acc2[i][grp * 4 + u], 8);
                    float v = h2 ? p.y : p.x;
                    if (bias) v += bias[col + u];
                    po[u] = v;
                }
                *(float4*)(C + (long)r * ldc + col) = o;
            }
        }
    }
}

// ---------------- HMMA 2-split GEMM (smooth paths): C = A @ B^T ----------------
template<int OUTMODE>   // 0 = fp32+bias, 1 = fp32 silu+bias
__global__ __launch_bounds__(256, 1) void gemm_mma(
    const bf16* __restrict__ A0, const bf16* __restrict__ A1,
    const bf16* __restrict__ B0, const bf16* __restrict__ B1,
    const float* __restrict__ bias, float* __restrict__ C,
    int K, int lda, int ldb, int ldc)
{
    extern __shared__ char dsm[];
    const int tid = threadIdx.x, wid = tid >> 5, lane = tid & 31;
    const int wm = wid & 1, wn = wid >> 1;
    const int bm = blockIdx.y * 128, bn = blockIdx.x * 128;
    const bf16* As[2] = {A0, A1};
    const bf16* Bs[2] = {B0, B1};

    uint32_t sb = (smem_u32(dsm) + 1023u) & ~1023u;
    const int nch = K >> 6;

    auto load_tile = [&](uint32_t st, const bf16* g, int ld, int c0){
#pragma unroll
        for (int t = 0; t < 4; t++){
            int c = tid + t * 256, r = c >> 3, c8 = c & 7;
            cp16(st + (uint32_t)(r * 128) + (uint32_t)(((c8 ^ (r & 7)) * 16)),
                 g + (size_t)r * ld + c0 + c8 * 8);
        }
    };
    auto load_chunk = [&](int stage, int k0){
        uint32_t st = sb + stage * 65536u;
#pragma unroll
        for (int sp = 0; sp < 2; sp++) load_tile(st + sp * 16384, As[sp] + (size_t)bm * lda, lda, k0);
#pragma unroll
        for (int sp = 0; sp < 2; sp++) load_tile(st + (2 + sp) * 16384, Bs[sp] + (size_t)bn * ldb, ldb, k0);
        cp_commit();
    };

    float acc[4][4][4];
#pragma unroll
    for (int i = 0; i < 4; i++)
#pragma unroll
        for (int j = 0; j < 4; j++)
#pragma unroll
            for (int u = 0; u < 4; u++) acc[i][j][u] = 0.0f;

    const int lr = lane & 15, lk = lane >> 4;

    load_chunk(0, 0);
    for (int c = 0; c < nch; c++){
        const int s = c & 1;
        if (c + 1 < nch){ load_chunk((c + 1) & 1, (c + 1) << 6); cp_wait<1>(); }
        else cp_wait<0>();
        __syncthreads();

        const uint32_t stg = sb + s * 65536u;
#pragma unroll
        for (int ks = 0; ks < 4; ks++){
            const int kc = ks * 2 + lk;
            uint32_t af[2][4][4], bfr[2][2][4];
#pragma unroll
            for (int sp = 0; sp < 2; sp++)
#pragma unroll
                for (int i = 0; i < 4; i++){
                    int r = wm * 64 + i * 16 + lr;
                    ldsm4(af[sp][i], stg + sp * 16384 + (uint32_t)(r * 128) + (uint32_t)(((kc ^ (r & 7)) * 16)));
                }
#pragma unroll
            for (int sp = 0; sp < 2; sp++)
#pragma unroll
                for (int j2 = 0; j2 < 2; j2++){
                    int rn = wn * 32 + j2 * 16 + lr;
                    ldsm4(bfr[sp][j2], stg + (2 + sp) * 16384 + (uint32_t)(rn * 128) + (uint32_t)(((kc ^ (rn & 7)) * 16)));
                }
#pragma unroll
            for (int i = 0; i < 4; i++)
#pragma unroll
                for (int j2 = 0; j2 < 2; j2++){
                    mma16816(acc[i][2*j2],   af[0][i], bfr[0][j2][0], bfr[0][j2][2]);
                    mma16816(acc[i][2*j2+1], af[0][i], bfr[0][j2][1], bfr[0][j2][3]);
                    mma16816(acc[i][2*j2],   af[0][i], bfr[1][j2][0], bfr[1][j2][2]);
                    mma16816(acc[i][2*j2+1], af[0][i], bfr[1][j2][1], bfr[1][j2][3]);
                    mma16816(acc[i][2*j2],   af[1][i], bfr[0][j2][0], bfr[0][j2][2]);
                    mma16816(acc[i][2*j2+1], af[1][i], bfr[0][j2][1], bfr[0][j2][3]);
                }
        }
        __syncthreads();
    }

    const int tr = lane >> 2, tc = (lane & 3) * 2;
#pragma unroll
    for (int i = 0; i < 4; i++)
#pragma unroll
        for (int h2 = 0; h2 < 2; h2++){
            const int row = bm + wm * 64 + i * 16 + tr + h2 * 8;
#pragma unroll
            for (int j = 0; j < 4; j++){
                const int col = bn + wn * 32 + j * 8 + tc;
                float v0 = acc[i][j][h2*2], v1 = acc[i][j][h2*2+1];
                if (bias){ v0 += bias[col]; v1 += bias[col+1]; }
                if (OUTMODE == 1){
                    v0 = v0 / (1.0f + expf(-v0));
                    v1 = v1 / (1.0f + expf(-v1));
                }
                *(float2*)(C + (size_t)row * ldc + col) = make_float2(v0, v1);
            }
        }
}

// ---------------- preprocessing ----------------
__global__ __launch_bounds__(256) void split2_kernel(const float2* __restrict__ in,
    bf16* __restrict__ h, bf16* __restrict__ l, int n2)
{
    int i = blockIdx.x * 256 + threadIdx.x;
    if (i >= n2) return;
    float2 v = in[i];
    bf16 h0,l0,h1,l1;
    split2v(v.x,h0,l0); split2v(v.y,h1,l1);
    ((uint32_t*)h)[i] = (uint32_t)__bfloat16_as_ushort(h0) | ((uint32_t)__bfloat16_as_ushort(h1) << 16);
    ((uint32_t*)l)[i] = (uint32_t)__bfloat16_as_ushort(l0) | ((uint32_t)__bfloat16_as_ushort(l1) << 16);
}

__global__ void tsplit_kernel(const float* __restrict__ in,
    bf16* __restrict__ o0, bf16* __restrict__ o1, int K, int N)
{
    __shared__ float t[32][33];
    int k0 = blockIdx.y * 32, n0 = blockIdx.x * 32;
    t[threadIdx.y][threadIdx.x] = in[(size_t)(k0 + threadIdx.y) * N + n0 + threadIdx.x];
    __syncthreads();
    float v = t[threadIdx.x][threadIdx.y];
    size_t o = (size_t)(n0 + threadIdx.y) * K + k0 + threadIdx.x;
    bf16 h, l; split2v(v, h, l);
    o0[o] = h; o1[o] = l;
}

// ---------------- stage-1 top-32 of 512 per (n, ht): register rescan ----------------
__global__ __launch_bounds__(256) void topk1_kernel()
{
    int n = blockIdx.x, w = threadIdx.x >> 5, lane = threadIdx.x & 31;
    const float* sc = g_scores + (size_t)n * 4096 + (size_t)w * 512;
    float v[16]; float lmax = -FLT_MAX; int lslot = 0;
#pragma unroll
    for (int i = 0; i < 16; i++){
        v[i] = sc[i * 32 + lane];
        if (v[i] > lmax){ lmax = v[i]; lslot = i; }
    }
    float outV = 0.0f; int outI = 0;
    const unsigned FULL = 0xffffffffu;
    for (int it = 0; it < 32; it++){
        float m = lmax; int mk = lslot * 32 + lane;
#pragma unroll
        for (int off = 16; off; off >>= 1){
            float om = __shfl_xor_sync(FULL, m, off);
            int   ok = __shfl_xor_sync(FULL, mk, off);
            if (om > m || (om == m && ok < mk)){ m = om; mk = ok; }
        }
        if (lane == it){ outV = m; outI = mk; }
        if ((mk & 31) == lane){
            int ds = mk >> 5;
#pragma unroll
            for (int i = 0; i < 16; i++) if (i == ds) v[i] = -FLT_MAX;
            lmax = -FLT_MAX; lslot = 0;
#pragma unroll
            for (int i = 0; i < 16; i++) if (v[i] > lmax){ lmax = v[i]; lslot = i; }
        }
    }
    size_t o = ((size_t)n * 8 + w) * KNN_K + lane;
    g_ts[o] = outV; g_ti[o] = outI;
}

// ---------------- stage-2: dominance pruning + counting selection (exact) ----------------
__constant__ unsigned short c_cand[128] = {
    0x000,0x001,0x002,0x003,0x004,0x005,0x006,0x007,0x008,0x009,0x00A,0x00B,0x00C,0x00D,0x00E,0x00F,
    0x010,0x011,0x012,0x013,0x014,0x015,0x016,0x017,0x018,0x019,0x01A,0x01B,0x01C,0x01D,0x01E,0x01F,
    0x100,0x101,0x102,0x103,0x104,0x105,0x106,0x107,0x108,0x109,0x10A,0x10B,0x10C,0x10D,0x10E,0x10F,
    0x200,0x201,0x202,0x203,0x204,0x205,0x206,0x207,0x208,0x209,
    0x300,0x301,0x302,0x303,0x304,0x305,0x306,0x307,
    0x400,0x401,0x402,0x403,0x404,0x405,
    0x500,0x501,0x502,0x503,0x504,
    0x600,0x601,0x602,0x603,
    0x700,0x701,0x702,0x703,
    0x800,0x801,0x802, 0x900,0x901,0x902,
    0xA00,0xA01, 0xB00,0xB01, 0xC00,0xC01, 0xD00,0xD01, 0xE00,0xE01, 0xF00,0xF01,
    0x1000,0x1100,0x1200,0x1300,0x1400,0x1500,0x1600,0x1700,
    0x1800,0x1900,0x1A00,0x1B00,0x1C00,0x1D00,0x1E00,0x1F00,
    0xFFFF,0xFFFF,0xFFFF,0xFFFF,0xFFFF,0xFFFF,0xFFFF,0xFFFF,0xFFFF };

__global__ __launch_bounds__(128) void topk2_kernel()
{
    int n = blockIdx.x, h = threadIdx.x >> 5, lane = threadIdx.x & 31;
    const unsigned FULL = 0xffffffffu;
    __shared__ unsigned long long skeys[4][128];
    __shared__ int si1[4][32], si2[4][32];

    size_t b1 = ((size_t)n * 8 + h * 2) * KNN_K;
    float s1 = g_ts[b1 + lane];
    float s2 = g_ts[b1 + KNN_K + lane];
    si1[h][lane] = g_ti[b1 + lane];
    si2[h][lane] = g_ti[b1 + KNN_K + lane];
    __syncwarp();

    float val[4]; unsigned long long key[4]; int ci_[4], cj_[4]; bool real[4];
#pragma unroll
    for (int s = 0; s < 4; s++){
        unsigned pk = c_cand[lane * 4 + s];
        int ci = (pk >> 8) & 31, cj = pk & 31;
        ci_[s] = ci; cj_[s] = cj;
        real[s] = (pk != 0xFFFFu);
        float v = __shfl_sync(FULL, s1, ci) + __shfl_sync(FULL, s2, cj);
        val[s] = v;
        unsigned u = __float_as_uint(v);
        unsigned sv = (u & 0x80000000u) ? ~u : (u | 0x80000000u);
        unsigned p = (unsigned)(ci * 32 + cj);
        key[s] = real[s] ? (((unsigned long long)sv << 32) | (unsigned long long)(1023u - p)) : 0ull;
        skeys[h][lane * 4 + s] = key[s];
    }
    __syncwarp();

    int cnt[4] = {0,0,0,0};
    for (int k2 = 0; k2 < 128; k2++){
        unsigned long long o = skeys[h][k2];
#pragma unroll
        for (int s = 0; s < 4; s++) cnt[s] += (o > key[s]);
    }
    bool sel[4];
#pragma unroll
    for (int s = 0; s < 4; s++) sel[s] = real[s] && (cnt[s] < 32);

    float m = -FLT_MAX;
#pragma unroll
    for (int s = 0; s < 4; s++) if (sel[s] && val[s] > m) m = val[s];
#pragma unroll
    for (int off = 16; off; off >>= 1) m = fmaxf(m, __shfl_xor_sync(FULL, m, off));
    float e[4], sum = 0.0f;
#pragma unroll
    for (int s = 0; s < 4; s++){ e[s] = sel[s] ? expf(val[s] - m) : 0.0f; sum += e[s]; }
#pragma unroll
    for (int off = 16; off; off >>= 1) sum += __shfl_xor_sync(FULL, sum, off);

    size_t ob = ((size_t)n * 4 + h) * KNN_K;
#pragma unroll
    for (int s = 0; s < 4; s++){
        if (sel[s]){
            g_cw[ob + cnt[s]] = e[s] / sum;
            g_ci[ob + cnt[s]] = si1[h][ci_[s]] * 512 + si2[h][cj_[s]];
        }
    }
}

// ---------------- gather + gate + 2-way split ----------------
__global__ __launch_bounds__(128) void gather_kernel(const float* __restrict__ values)
{
    int n = blockIdx.x, t = threadIdx.x;
    __shared__ float sw[128]; __shared__ int sid[128];
    sw[t]  = g_cw[(size_t)n * 128 + t];
    sid[t] = g_ci[(size_t)n * 128 + t];
    __syncthreads();
    float4 acc = {0.f,0.f,0.f,0.f};
#pragma unroll 4
    for (int r = 0; r < 128; r++){
        float wr = sw[r];
        const float4 v = *((const float4*)(values + (size_t)sid[r] * 512) + t);
        acc.x += wr*v.x; acc.y += wr*v.y; acc.z += wr*v.z; acc.w += wr*v.w;
    }
    float4 g = *(const float4*)(g_gate + (size_t)n * 512 + t * 4);
    float o[4] = {acc.x*g.x, acc.y*g.y, acc.z*g.z, acc.w*g.w};
    uint32_t hp[2], lp[2];
#pragma unroll
    for (int u = 0; u < 2; u++){
        bf16 h0,l0,h1,l1;
        split2v(o[u*2],h0,l0); split2v(o[u*2+1],h1,l1);
        hp[u] = (uint32_t)__bfloat16_as_ushort(h0) | ((uint32_t)__bfloat16_as_ushort(h1) << 16);
        lp[u] = (uint32_t)__bfloat16_as_ushort(l0) | ((uint32_t)__bfloat16_as_ushort(l1) << 16);
    }
    *(uint2*)(&g_h2[0][(size_t)n * 512 + t * 4]) = make_uint2(hp[0], hp[1]);
    *(uint2*)(&g_h2[1][(size_t)n * 512 + t * 4]) = make_uint2(lp[0], lp[1]);
}

// ---------------- launch ----------------
extern "C" void kernel_launch(void* const* d_in, const int* in_sizes, int n_in,
                              void* d_out, int out_size)
{
    const float* x      = (const float*)d_in[0];
    const float* Wq     = (const float*)d_in[1];
    const float* bq     = (const float*)d_in[2];
    const float* keys   = (const float*)d_in[3];
    const float* values = (const float*)d_in[4];
    const float* Ws     = (const float*)d_in[5];
    const float* bs     = (const float*)d_in[6];
    const float* Wv     = (const float*)d_in[7];
    const float* bv     = (const float*)d_in[8];
    float* out          = (float*)d_out;

    const int SMEM2 = 2 * 2 * 32768;
    cudaFuncSetAttribute(gemm_mma<0>, cudaFuncAttributeMaxDynamicSharedMemorySize, SMEM2);
    cudaFuncSetAttribute(gemm_mma<1>, cudaFuncAttributeMaxDynamicSharedMemorySize, SMEM2);

    float *q, *scores, *gate;
    bf16 *x2[2], *ws2[2], *wv2[2], *h2[2];
    cudaGetSymbolAddress((void**)&q, g_q);
    cudaGetSymbolAddress((void**)&scores, g_scores);
    cudaGetSymbolAddress((void**)&gate, g_gate);
    {
        bf16* base;
        cudaGetSymbolAddress((void**)&base, g_x2);  for (int i=0;i<2;i++) x2[i]  = base + (size_t)i*2048*1024;
        cudaGetSymbolAddress((void**)&base, g_ws2); for (int i=0;i<2;i++) ws2[i] = base + (size_t)i*512*1024;
        cudaGetSymbolAddress((void**)&base, g_wv2); for (int i=0;i<2;i++) wv2[i] = base + (size_t)i*1024*512;
        cudaGetSymbolAddress((void**)&base, g_h2);  for (int i=0;i<2;i++) h2[i]  = base + (size_t)i*2048*512;
    }

    // preprocessing for HMMA smooth paths
    split2_kernel<<<4096, 256>>>((const float2*)x, x2[0], x2[1], 2048*1024/2);
    tsplit_kernel<<<dim3(16, 32), dim3(32, 32)>>>(Ws, ws2[0], ws2[1], 1024, 512);
    tsplit_kernel<<<dim3(32, 16), dim3(32, 32)>>>(Wv, wv2[0], wv2[1], 512, 1024);

    // 1) q = x @ Wq + bq  (fp32, f32x2, exact, 128x128 tiles)
    gemm_f2<false><<<dim3(2048/128, 2048/128, 1), 256>>>(
        x, Wq, bq, q, 1024, 1024, 2048, 2048, 0, 0, 0);

    // 2) scores = q @ keys^T  (8 batches, fp32 f32x2, exact)
    gemm_f2<true><<<dim3(512/128, 2048/128, 8), 256>>>(
        q, keys, nullptr, scores, 256, 2048, 256, 4096, 256L, 512L*256L, 512L);

    // 3) stage-1 top-32   4) stage-2 + softmax
    topk1_kernel<<<2048, 256>>>();
    topk2_kernel<<<2048, 128>>>();

    // 5) gate = silu(x @ Ws + bs)  (HMMA 2-split)
    gemm_mma<1><<<dim3(4,16,1), 256, SMEM2>>>(
        x2[0], x2[1], ws2[0], ws2[1], bs, gate, 1024, 1024, 1024, 512);

    // 6) hidden = gate * gathered values
    gather_kernel<<<2048, 128>>>(values);

    // 7) out = hidden @ Wv + bv  (HMMA 2-split)
    gemm_mma<0><<<dim3(8,16,1), 256, SMEM2>>>(
        h2[0], h2[1], wv2[0], wv2[1], bv, out, 512, 512, 512, 1024);
}

// round 9
// speedup vs baseline: 1.5668x; 1.0359x over previous
#include <cuda_runtime.h>
#include <cuda_bf16.h>
#include <math.h>
#include <float.h>
#include <string.h>
#include <stdint.h>

#define KNN_K 32
typedef __nv_bfloat16 bf16;

// ---------------- scratch ----------------
__device__ __align__(16) float g_q[2048*2048];
__device__ __align__(16) float g_scores[2048*4096];
__device__ __align__(16) bf16 g_x2[2][2048*1024];
__device__ __align__(16) bf16 g_ws2[2][512*1024];
__device__ __align__(16) bf16 g_wv2[2][1024*512];
__device__ __align__(16) bf16 g_h2[2][2048*512];
__device__ __align__(16) float g_ts[2048*8*32];
__device__ int   g_ti[2048*8*32];
__device__ __align__(16) float g_cw[2048*4*32];
__device__ int   g_ci[2048*4*32];
__device__ __align__(16) float g_gate[2048*512];

// ---------------- helpers ----------------
__device__ __forceinline__ uint32_t smem_u32(const void* p){ return (uint32_t)__cvta_generic_to_shared(p); }
__device__ __forceinline__ void cp16(uint32_t dst, const void* src){
    asm volatile("cp.async.cg.shared.global [%0], [%1], 16;\n" :: "r"(dst), "l"(src));
}
__device__ __forceinline__ void cp_commit(){ asm volatile("cp.async.commit_group;\n" ::: "memory"); }
template<int N> __device__ __forceinline__ void cp_wait(){ asm volatile("cp.async.wait_group %0;\n" :: "n"(N) : "memory"); }
__device__ __forceinline__ void ldsm4(uint32_t (&r)[4], uint32_t addr){
    asm volatile("ldmatrix.sync.aligned.m8n8.x4.shared.b16 {%0,%1,%2,%3}, [%4];"
        : "=r"(r[0]), "=r"(r[1]), "=r"(r[2]), "=r"(r[3]) : "r"(addr));
}
__device__ __forceinline__ void mma16816(float (&d)[4], const uint32_t (&a)[4], uint32_t b0, uint32_t b1){
    asm volatile("mma.sync.aligned.m16n8k16.row.col.f32.bf16.bf16.f32 "
        "{%0,%1,%2,%3}, {%4,%5,%6,%7}, {%8,%9}, {%0,%1,%2,%3};"
        : "+f"(d[0]), "+f"(d[1]), "+f"(d[2]), "+f"(d[3])
        : "r"(a[0]), "r"(a[1]), "r"(a[2]), "r"(a[3]), "r"(b0), "r"(b1));
}
__device__ __forceinline__ void ffma2(uint64_t& d, uint64_t a, uint64_t b){
    asm("fma.rn.f32x2 %0, %1, %2, %3;" : "=l"(d) : "l"(a), "l"(b), "l"(d));
}
__device__ __forceinline__ uint64_t pack2(float v){
    uint64_t d; asm("mov.b64 %0, {%1, %1};" : "=l"(d) : "f"(v)); return d;
}
__device__ __forceinline__ void split2v(float v, bf16& h, bf16& l){
    h = __float2bfloat16(v);
    l = __float2bfloat16(v - __bfloat162float(h));
}

// ---------------- fp32 GEMM via f32x2: 128x256 tile, 512 thr, warp-uniform A rows ----
// C = A @ B (+bias); BT: B is [N][K] row-major -> C = A @ B^T
// Exact per-output k-ascending fp32 fma chains (bitwise-stable across rounds).
template<bool BT>
__global__ __launch_bounds__(512) void gemm_f2(
    const float* __restrict__ A, const float* __restrict__ B,
    const float* __restrict__ bias, float* __restrict__ C,
    int K, int lda, int ldb, int ldc, long sA, long sB, long sC)
{
    constexpr int BM = 128, BN = 256, BK = 16;
    __shared__ float As[BK][BM];     // 8 KB
    __shared__ float Bs[BK][BN];     // 16 KB

    A += (long)blockIdx.z * sA;
    B += (long)blockIdx.z * sB;
    C += (long)blockIdx.z * sC;

    const int bm = blockIdx.y * BM, bn = blockIdx.x * BN;
    const int tid = threadIdx.x;
    const int lane = tid & 31, wid = tid >> 5;      // 16 warps; warp-uniform rows

    uint64_t acc2[4][8];    // [row-pair i: rows wid*8+2i,+2i+1][col j: j<4 -> lane*4+j, j>=4 -> 128+lane*4+j-4]
#pragma unroll
    for (int i = 0; i < 4; i++)
#pragma unroll
        for (int j = 0; j < 8; j++) acc2[i][j] = 0ull;

    // register-prefetch double buffering
    const int ar = tid >> 2, ac = (tid & 3) * 4;    // A: row ar (0..127), cols ac..ac+3
    float4 ra, rb0, rb1;
    auto ldg = [&](int k0){
        ra = *(const float4*)(A + (long)(bm + ar) * lda + k0 + ac);
        if (BT){
            rb0 = *(const float4*)(B + (long)(bn + ar) * ldb + k0 + ac);
            rb1 = *(const float4*)(B + (long)(bn + ar + 128) * ldb + k0 + ac);
        } else {
            const int bk = tid >> 6, bc = (tid & 63) * 4;     // bk 0..7
            rb0 = *(const float4*)(B + (long)(k0 + bk) * ldb + bn + bc);
            rb1 = *(const float4*)(B + (long)(k0 + bk + 8) * ldb + bn + bc);
        }
    };
    auto sts = [&](){
        As[ac + 0][ar] = ra.x; As[ac + 1][ar] = ra.y;
        As[ac + 2][ar] = ra.z; As[ac + 3][ar] = ra.w;
        if (BT){
            Bs[ac + 0][ar] = rb0.x; Bs[ac + 1][ar] = rb0.y;
            Bs[ac + 2][ar] = rb0.z; Bs[ac + 3][ar] = rb0.w;
            Bs[ac + 0][ar + 128] = rb1.x; Bs[ac + 1][ar + 128] = rb1.y;
            Bs[ac + 2][ar + 128] = rb1.z; Bs[ac + 3][ar + 128] = rb1.w;
        } else {
            const int bk = tid >> 6, bc = (tid & 63) * 4;
            *(float4*)&Bs[bk][bc]     = rb0;
            *(float4*)&Bs[bk + 8][bc] = rb1;
        }
    };

    const int nch = K / BK;
    ldg(0);
    for (int c = 0; c < nch; c++){
        sts();
        __syncthreads();
        if (c + 1 < nch) ldg((c + 1) * BK);

#pragma unroll
        for (int kk = 0; kk < BK; kk++){
            uint64_t a2[4];
#pragma unroll
            for (int i = 0; i < 4; i++)         // LDS.64 broadcast (warp-uniform address)
                a2[i] = *(const uint64_t*)&As[kk][wid * 8 + 2 * i];
            float4 b40 = *(const float4*)&Bs[kk][lane * 4];         // conflict-free LDS.128
            float4 b41 = *(const float4*)&Bs[kk][128 + lane * 4];
            uint64_t b2[8] = {pack2(b40.x), pack2(b40.y), pack2(b40.z), pack2(b40.w),
                              pack2(b41.x), pack2(b41.y), pack2(b41.z), pack2(b41.w)};
#pragma unroll
            for (int i = 0; i < 4; i++)
#pragma unroll
                for (int j = 0; j < 8; j++)
                    ffma2(acc2[i][j], a2[i], b2[j]);
        }
        __syncthreads();
    }

    // epilogue
#pragma unroll
    for (int i = 0; i < 4; i++){
#pragma unroll
        for (int h2 = 0; h2 < 2; h2++){
            const int r = bm + wid * 8 + i * 2 + h2;
#pragma unroll
            for (int grp = 0; grp < 2; grp++){
                const int col = bn + grp * 128 + lane * 4;
                float4 o;
                float* po = &o.x;
#pragma unroll
                for (int u = 0; u < 4; u++){
                    float2 p; memcpy(&p, &acc2[i][grp * 4 + u], 8);
                    float v = h2 ? p.y : p.x;
                    if (bias) v += bias[col + u];
                    po[u] = v;
                }
                *(float4*)(C + (long)r * ldc + col) = o;
            }
        }
    }
}

// ---------------- HMMA 2-split GEMM (smooth paths): C = A @ B^T ----------------
template<int OUTMODE>   // 0 = fp32+bias, 1 = fp32 silu+bias
__global__ __launch_bounds__(256, 1) void gemm_mma(
    const bf16* __restrict__ A0, const bf16* __restrict__ A1,
    const bf16* __restrict__ B0, const bf16* __restrict__ B1,
    const float* __restrict__ bias, float* __restrict__ C,
    int K, int lda, int ldb, int ldc)
{
    extern __shared__ char dsm[];
    const int tid = threadIdx.x, wid = tid >> 5, lane = tid & 31;
    const int wm = wid & 1, wn = wid >> 1;
    const int bm = blockIdx.y * 128, bn = blockIdx.x * 128;
    const bf16* As[2] = {A0, A1};
    const bf16* Bs[2] = {B0, B1};

    uint32_t sb = (smem_u32(dsm) + 1023u) & ~1023u;
    const int nch = K >> 6;

    auto load_tile = [&](uint32_t st, const bf16* g, int ld, int c0){
#pragma unroll
        for (int t = 0; t < 4; t++){
            int c = tid + t * 256, r = c >> 3, c8 = c & 7;
            cp16(st + (uint32_t)(r * 128) + (uint32_t)(((c8 ^ (r & 7)) * 16)),
                 g + (size_t)r * ld + c0 + c8 * 8);
        }
    };
    auto load_chunk = [&](int stage, int k0){
        uint32_t st = sb + stage * 65536u;
#pragma unroll
        for (int sp = 0; sp < 2; sp++) load_tile(st + sp * 16384, As[sp] + (size_t)bm * lda, lda, k0);
#pragma unroll
        for (int sp = 0; sp < 2; sp++) load_tile(st + (2 + sp) * 16384, Bs[sp] + (size_t)bn * ldb, ldb, k0);
        cp_commit();
    };

    float acc[4][4][4];
#pragma unroll
    for (int i = 0; i < 4; i++)
#pragma unroll
        for (int j = 0; j < 4; j++)
#pragma unroll
            for (int u = 0; u < 4; u++) acc[i][j][u] = 0.0f;

    const int lr = lane & 15, lk = lane >> 4;

    load_chunk(0, 0);
    for (int c = 0; c < nch; c++){
        const int s = c & 1;
        if (c + 1 < nch){ load_chunk((c + 1) & 1, (c + 1) << 6); cp_wait<1>(); }
        else cp_wait<0>();
        __syncthreads();

        const uint32_t stg = sb + s * 65536u;
#pragma unroll
        for (int ks = 0; ks < 4; ks++){
            const int kc = ks * 2 + lk;
            uint32_t af[2][4][4], bfr[2][2][4];
#pragma unroll
            for (int sp = 0; sp < 2; sp++)
#pragma unroll
                for (int i = 0; i < 4; i++){
                    int r = wm * 64 + i * 16 + lr;
                    ldsm4(af[sp][i], stg + sp * 16384 + (uint32_t)(r * 128) + (uint32_t)(((kc ^ (r & 7)) * 16)));
                }
#pragma unroll
            for (int sp = 0; sp < 2; sp++)
#pragma unroll
                for (int j2 = 0; j2 < 2; j2++){
                    int rn = wn * 32 + j2 * 16 + lr;
                    ldsm4(bfr[sp][j2], stg + (2 + sp) * 16384 + (uint32_t)(rn * 128) + (uint32_t)(((kc ^ (rn & 7)) * 16)));
                }
#pragma unroll
            for (int i = 0; i < 4; i++)
#pragma unroll
                for (int j2 = 0; j2 < 2; j2++){
                    mma16816(acc[i][2*j2],   af[0][i], bfr[0][j2][0], bfr[0][j2][2]);
                    mma16816(acc[i][2*j2+1], af[0][i], bfr[0][j2][1], bfr[0][j2][3]);
                    mma16816(acc[i][2*j2],   af[0][i], bfr[1][j2][0], bfr[1][j2][2]);
                    mma16816(acc[i][2*j2+1], af[0][i], bfr[1][j2][1], bfr[1][j2][3]);
                    mma16816(acc[i][2*j2],   af[1][i], bfr[0][j2][0], bfr[0][j2][2]);
                    mma16816(acc[i][2*j2+1], af[1][i], bfr[0][j2][1], bfr[0][j2][3]);
                }
        }
        __syncthreads();
    }

    const int tr = lane >> 2, tc = (lane & 3) * 2;
#pragma unroll
    for (int i = 0; i < 4; i++)
#pragma unroll
        for (int h2 = 0; h2 < 2; h2++){
            const int row = bm + wm * 64 + i * 16 + tr + h2 * 8;
#pragma unroll
            for (int j = 0; j < 4; j++){
                const int col = bn + wn * 32 + j * 8 + tc;
                float v0 = acc[i][j][h2*2], v1 = acc[i][j][h2*2+1];
                if (bias){ v0 += bias[col]; v1 += bias[col+1]; }
                if (OUTMODE == 1){
                    v0 = v0 / (1.0f + expf(-v0));
                    v1 = v1 / (1.0f + expf(-v1));
                }
                *(float2*)(C + (size_t)row * ldc + col) = make_float2(v0, v1);
            }
        }
}

// ---------------- preprocessing ----------------
__global__ __launch_bounds__(256) void split2_kernel(const float2* __restrict__ in,
    bf16* __restrict__ h, bf16* __restrict__ l, int n2)
{
    int i = blockIdx.x * 256 + threadIdx.x;
    if (i >= n2) return;
    float2 v = in[i];
    bf16 h0,l0,h1,l1;
    split2v(v.x,h0,l0); split2v(v.y,h1,l1);
    ((uint32_t*)h)[i] = (uint32_t)__bfloat16_as_ushort(h0) | ((uint32_t)__bfloat16_as_ushort(h1) << 16);
    ((uint32_t*)l)[i] = (uint32_t)__bfloat16_as_ushort(l0) | ((uint32_t)__bfloat16_as_ushort(l1) << 16);
}

__global__ void tsplit_kernel(const float* __restrict__ in,
    bf16* __restrict__ o0, bf16* __restrict__ o1, int K, int N)
{
    __shared__ float t[32][33];
    int k0 = blockIdx.y * 32, n0 = blockIdx.x * 32;
    t[threadIdx.y][threadIdx.x] = in[(size_t)(k0 + threadIdx.y) * N + n0 + threadIdx.x];
    __syncthreads();
    float v = t[threadIdx.x][threadIdx.y];
    size_t o = (size_t)(n0 + threadIdx.y) * K + k0 + threadIdx.x;
    bf16 h, l; split2v(v, h, l);
    o0[o] = h; o1[o] = l;
}

// ---------------- stage-1 top-32 of 512 per (n, ht): register rescan ----------------
__global__ __launch_bounds__(256) void topk1_kernel()
{
    int n = blockIdx.x, w = threadIdx.x >> 5, lane = threadIdx.x & 31;
    const float* sc = g_scores + (size_t)n * 4096 + (size_t)w * 512;
    float v[16]; float lmax = -FLT_MAX; int lslot = 0;
#pragma unroll
    for (int i = 0; i < 16; i++){
        v[i] = sc[i * 32 + lane];
        if (v[i] > lmax){ lmax = v[i]; lslot = i; }
    }
    float outV = 0.0f; int outI = 0;
    const unsigned FULL = 0xffffffffu;
    for (int it = 0; it < 32; it++){
        float m = lmax; int mk = lslot * 32 + lane;
#pragma unroll
        for (int off = 16; off; off >>= 1){
            float om = __shfl_xor_sync(FULL, m, off);
            int   ok = __shfl_xor_sync(FULL, mk, off);
            if (om > m || (om == m && ok < mk)){ m = om; mk = ok; }
        }
        if (lane == it){ outV = m; outI = mk; }
        if ((mk & 31) == lane){
            int ds = mk >> 5;
#pragma unroll
            for (int i = 0; i < 16; i++) if (i == ds) v[i] = -FLT_MAX;
            lmax = -FLT_MAX; lslot = 0;
#pragma unroll
            for (int i = 0; i < 16; i++) if (v[i] > lmax){ lmax = v[i]; lslot = i; }
        }
    }
    size_t o = ((size_t)n * 8 + w) * KNN_K + lane;
    g_ts[o] = outV; g_ti[o] = outI;
}

// ---------------- stage-2: dominance pruning + counting selection (exact) ----------------
__constant__ unsigned short c_cand[128] = {
    0x000,0x001,0x002,0x003,0x004,0x005,0x006,0x007,0x008,0x009,0x00A,0x00B,0x00C,0x00D,0x00E,0x00F,
    0x010,0x011,0x012,0x013,0x014,0x015,0x016,0x017,0x018,0x019,0x01A,0x01B,0x01C,0x01D,0x01E,0x01F,
    0x100,0x101,0x102,0x103,0x104,0x105,0x106,0x107,0x108,0x109,0x10A,0x10B,0x10C,0x10D,0x10E,0x10F,
    0x200,0x201,0x202,0x203,0x204,0x205,0x206,0x207,0x208,0x209,
    0x300,0x301,0x302,0x303,0x304,0x305,0x306,0x307,
    0x400,0x401,0x402,0x403,0x404,0x405,
    0x500,0x501,0x502,0x503,0x504,
    0x600,0x601,0x602,0x603,
    0x700,0x701,0x702,0x703,
    0x800,0x801,0x802, 0x900,0x901,0x902,
    0xA00,0xA01, 0xB00,0xB01, 0xC00,0xC01, 0xD00,0xD01, 0xE00,0xE01, 0xF00,0xF01,
    0x1000,0x1100,0x1200,0x1300,0x1400,0x1500,0x1600,0x1700,
    0x1800,0x1900,0x1A00,0x1B00,0x1C00,0x1D00,0x1E00,0x1F00,
    0xFFFF,0xFFFF,0xFFFF,0xFFFF,0xFFFF,0xFFFF,0xFFFF,0xFFFF,0xFFFF };

__global__ __launch_bounds__(128) void topk2_kernel()
{
    int n = blockIdx.x, h = threadIdx.x >> 5, lane = threadIdx.x & 31;
    const unsigned FULL = 0xffffffffu;
    __shared__ unsigned long long skeys[4][128];
    __shared__ int si1[4][32], si2[4][32];

    size_t b1 = ((size_t)n * 8 + h * 2) * KNN_K;
    float s1 = g_ts[b1 + lane];
    float s2 = g_ts[b1 + KNN_K + lane];
    si1[h][lane] = g_ti[b1 + lane];
    si2[h][lane] = g_ti[b1 + KNN_K + lane];
    __syncwarp();

    float val[4]; unsigned long long key[4]; int ci_[4], cj_[4]; bool real[4];
#pragma unroll
    for (int s = 0; s < 4; s++){
        unsigned pk = c_cand[lane * 4 + s];
        int ci = (pk >> 8) & 31, cj = pk & 31;
        ci_[s] = ci; cj_[s] = cj;
        real[s] = (pk != 0xFFFFu);
        float v = __shfl_sync(FULL, s1, ci) + __shfl_sync(FULL, s2, cj);
        val[s] = v;
        unsigned u = __float_as_uint(v);
        unsigned sv = (u & 0x80000000u) ? ~u : (u | 0x80000000u);
        unsigned p = (unsigned)(ci * 32 + cj);
        key[s] = real[s] ? (((unsigned long long)sv << 32) | (unsigned long long)(1023u - p)) : 0ull;
        skeys[h][lane * 4 + s] = key[s];
    }
    __syncwarp();

    int cnt[4] = {0,0,0,0};
    for (int k2 = 0; k2 < 128; k2++){
        unsigned long long o = skeys[h][k2];
#pragma unroll
        for (int s = 0; s < 4; s++) cnt[s] += (o > key[s]);
    }
    bool sel[4];
#pragma unroll
    for (int s = 0; s < 4; s++) sel[s] = real[s] && (cnt[s] < 32);

    float m = -FLT_MAX;
#pragma unroll
    for (int s = 0; s < 4; s++) if (sel[s] && val[s] > m) m = val[s];
#pragma unroll
    for (int off = 16; off; off >>= 1) m = fmaxf(m, __shfl_xor_sync(FULL, m, off));
    float e[4], sum = 0.0f;
#pragma unroll
    for (int s = 0; s < 4; s++){ e[s] = sel[s] ? expf(val[s] - m) : 0.0f; sum += e[s]; }
#pragma unroll
    for (int off = 16; off; off >>= 1) sum += __shfl_xor_sync(FULL, sum, off);

    size_t ob = ((size_t)n * 4 + h) * KNN_K;
#pragma unroll
    for (int s = 0; s < 4; s++){
        if (sel[s]){
            g_cw[ob + cnt[s]] = e[s] / sum;
            g_ci[ob + cnt[s]] = si1[h][ci_[s]] * 512 + si2[h][cj_[s]];
        }
    }
}

// ---------------- gather + gate + 2-way split ----------------
__global__ __launch_bounds__(128) void gather_kernel(const float* __restrict__ values)
{
    int n = blockIdx.x, t = threadIdx.x;
    __shared__ float sw[128]; __shared__ int sid[128];
    sw[t]  = g_cw[(size_t)n * 128 + t];
    sid[t] = g_ci[(size_t)n * 128 + t];
    __syncthreads();
    float4 acc = {0.f,0.f,0.f,0.f};
#pragma unroll 4
    for (int r = 0; r < 128; r++){
        float wr = sw[r];
        const float4 v = *((const float4*)(values + (size_t)sid[r] * 512) + t);
        acc.x += wr*v.x; acc.y += wr*v.y; acc.z += wr*v.z; acc.w += wr*v.w;
    }
    float4 g = *(const float4*)(g_gate + (size_t)n * 512 + t * 4);
    float o[4] = {acc.x*g.x, acc.y*g.y, acc.z*g.z, acc.w*g.w};
    uint32_t hp[2], lp[2];
#pragma unroll
    for (int u = 0; u < 2; u++){
        bf16 h0,l0,h1,l1;
        split2v(o[u*2],h0,l0); split2v(o[u*2+1],h1,l1);
        hp[u] = (uint32_t)__bfloat16_as_ushort(h0) | ((uint32_t)__bfloat16_as_ushort(h1) << 16);
        lp[u] = (uint32_t)__bfloat16_as_ushort(l0) | ((uint32_t)__bfloat16_as_ushort(l1) << 16);
    }
    *(uint2*)(&g_h2[0][(size_t)n * 512 + t * 4]) = make_uint2(hp[0], hp[1]);
    *(uint2*)(&g_h2[1][(size_t)n * 512 + t * 4]) = make_uint2(lp[0], lp[1]);
}

// ---------------- launch ----------------
extern "C" void kernel_launch(void* const* d_in, const int* in_sizes, int n_in,
                              void* d_out, int out_size)
{
    const float* x      = (const float*)d_in[0];
    const float* Wq     = (const float*)d_in[1];
    const float* bq     = (const float*)d_in[2];
    const float* keys   = (const float*)d_in[3];
    const float* values = (const float*)d_in[4];
    const float* Ws     = (const float*)d_in[5];
    const float* bs     = (const float*)d_in[6];
    const float* Wv     = (const float*)d_in[7];
    const float* bv     = (const float*)d_in[8];
    float* out          = (float*)d_out;

    const int SMEM2 = 2 * 2 * 32768;
    cudaFuncSetAttribute(gemm_mma<0>, cudaFuncAttributeMaxDynamicSharedMemorySize, SMEM2);
    cudaFuncSetAttribute(gemm_mma<1>, cudaFuncAttributeMaxDynamicSharedMemorySize, SMEM2);

    float *q, *scores, *gate;
    bf16 *x2[2], *ws2[2], *wv2[2], *h2[2];
    cudaGetSymbolAddress((void**)&q, g_q);
    cudaGetSymbolAddress((void**)&scores, g_scores);
    cudaGetSymbolAddress((void**)&gate, g_gate);
    {
        bf16* base;
        cudaGetSymbolAddress((void**)&base, g_x2);  for (int i=0;i<2;i++) x2[i]  = base + (size_t)i*2048*1024;
        cudaGetSymbolAddress((void**)&base, g_ws2); for (int i=0;i<2;i++) ws2[i] = base + (size_t)i*512*1024;
        cudaGetSymbolAddress((void**)&base, g_wv2); for (int i=0;i<2;i++) wv2[i] = base + (size_t)i*1024*512;
        cudaGetSymbolAddress((void**)&base, g_h2);  for (int i=0;i<2;i++) h2[i]  = base + (size_t)i*2048*512;
    }

    // preprocessing for HMMA smooth paths
    split2_kernel<<<4096, 256>>>((const float2*)x, x2[0], x2[1], 2048*1024/2);
    tsplit_kernel<<<dim3(16, 32), dim3(32, 32)>>>(Ws, ws2[0], ws2[1], 1024, 512);
    tsplit_kernel<<<dim3(32, 16), dim3(32, 32)>>>(Wv, wv2[0], wv2[1], 512, 1024);

    // 1) q = x @ Wq + bq  (fp32, f32x2, exact, 128x256 tiles, 512 thr)
    gemm_f2<false><<<dim3(2048/256, 2048/128, 1), 512>>>(
        x, Wq, bq, q, 1024, 1024, 2048, 2048, 0, 0, 0);

    // 2) scores = q @ keys^T  (8 batches, fp32 f32x2, exact)
    gemm_f2<true><<<dim3(512/256, 2048/128, 8), 512>>>(
        q, keys, nullptr, scores, 256, 2048, 256, 4096, 256L, 512L*256L, 512L);

    // 3) stage-1 top-32   4) stage-2 + softmax
    topk1_kernel<<<2048, 256>>>();
    topk2_kernel<<<2048, 128>>>();

    // 5) gate = silu(x @ Ws + bs)  (HMMA 2-split)
    gemm_mma<1><<<dim3(4,16,1), 256, SMEM2>>>(
        x2[0], x2[1], ws2[0], ws2[1], bs, gate, 1024, 1024, 1024, 512);

    // 6) hidden = gate * gathered values
    gather_kernel<<<2048, 128>>>(values);

    // 7) out = hidden @ Wv + bv  (HMMA 2-split)
    gemm_mma<0><<<dim3(8,16,1), 256, SMEM2>>>(
        h2[0], h2[1], wv2[0], wv2[1], bv, out, 512, 512, 512, 1024);
}

// round 10
// speedup vs baseline: 1.5776x; 1.0069x over previous
#include <cuda_runtime.h>
#include <cuda_bf16.h>
#include <math.h>
#include <float.h>
#include <string.h>
#include <stdint.h>

#define KNN_K 32
typedef __nv_bfloat16 bf16;

// ---------------- scratch ----------------
__device__ __align__(16) float g_q[2048*2048];
__device__ __align__(16) float g_scores[2048*4096];
__device__ __align__(16) bf16 g_wv2[2][1024*512];
__device__ __align__(16) bf16 g_h2[2][2048*512];
__device__ __align__(16) float g_gate[2048*512];

// ---------------- helpers ----------------
__device__ __forceinline__ uint32_t smem_u32(const void* p){ return (uint32_t)__cvta_generic_to_shared(p); }
__device__ __forceinline__ void cp16(uint32_t dst, const void* src){
    asm volatile("cp.async.cg.shared.global [%0], [%1], 16;\n" :: "r"(dst), "l"(src));
}
__device__ __forceinline__ void cp_commit(){ asm volatile("cp.async.commit_group;\n" ::: "memory"); }
template<int N> __device__ __forceinline__ void cp_wait(){ asm volatile("cp.async.wait_group %0;\n" :: "n"(N) : "memory"); }
__device__ __forceinline__ void ldsm4(uint32_t (&r)[4], uint32_t addr){
    asm volatile("ldmatrix.sync.aligned.m8n8.x4.shared.b16 {%0,%1,%2,%3}, [%4];"
        : "=r"(r[0]), "=r"(r[1]), "=r"(r[2]), "=r"(r[3]) : "r"(addr));
}
__device__ __forceinline__ void mma16816(float (&d)[4], const uint32_t (&a)[4], uint32_t b0, uint32_t b1){
    asm volatile("mma.sync.aligned.m16n8k16.row.col.f32.bf16.bf16.f32 "
        "{%0,%1,%2,%3}, {%4,%5,%6,%7}, {%8,%9}, {%0,%1,%2,%3};"
        : "+f"(d[0]), "+f"(d[1]), "+f"(d[2]), "+f"(d[3])
        : "r"(a[0]), "r"(a[1]), "r"(a[2]), "r"(a[3]), "r"(b0), "r"(b1));
}
__device__ __forceinline__ void ffma2(uint64_t& d, uint64_t a, uint64_t b){
    asm("fma.rn.f32x2 %0, %1, %2, %3;" : "=l"(d) : "l"(a), "l"(b), "l"(d));
}
__device__ __forceinline__ uint64_t pack2(float v){
    uint64_t d; asm("mov.b64 %0, {%1, %1};" : "=l"(d) : "f"(v)); return d;
}
__device__ __forceinline__ void split2v(float v, bf16& h, bf16& l){
    h = __float2bfloat16(v);
    l = __float2bfloat16(v - __bfloat162float(h));
}

// ---------------- q-GEMM: fp32 f32x2, 128x256 tile, 512 thr (verbatim R9 body) ------
__global__ __launch_bounds__(512) void gemm_q(
    const float* __restrict__ A, const float* __restrict__ B,
    const float* __restrict__ bias, float* __restrict__ C)
{
    constexpr int BM = 128, BN = 256, BK = 16;
    const int K = 1024, lda = 1024, ldb = 2048, ldc = 2048;
    __shared__ float As[BK][BM];
    __shared__ float Bs[BK][BN];

    const int bm = blockIdx.y * BM, bn = blockIdx.x * BN;
    const int tid = threadIdx.x;
    const int lane = tid & 31, wid = tid >> 5;

    uint64_t acc2[4][8];
#pragma unroll
    for (int i = 0; i < 4; i++)
#pragma unroll
        for (int j = 0; j < 8; j++) acc2[i][j] = 0ull;

    const int ar = tid >> 2, ac = (tid & 3) * 4;
    float4 ra, rb0, rb1;
    auto ldg = [&](int k0){
        ra = *(const float4*)(A + (long)(bm + ar) * lda + k0 + ac);
        const int bk = tid >> 6, bc = (tid & 63) * 4;
        rb0 = *(const float4*)(B + (long)(k0 + bk) * ldb + bn + bc);
        rb1 = *(const float4*)(B + (long)(k0 + bk + 8) * ldb + bn + bc);
    };
    auto sts = [&](){
        As[ac + 0][ar] = ra.x; As[ac + 1][ar] = ra.y;
        As[ac + 2][ar] = ra.z; As[ac + 3][ar] = ra.w;
        const int bk = tid >> 6, bc = (tid & 63) * 4;
        *(float4*)&Bs[bk][bc]     = rb0;
        *(float4*)&Bs[bk + 8][bc] = rb1;
    };

    const int nch = K / BK;
    ldg(0);
    for (int c = 0; c < nch; c++){
        sts();
        __syncthreads();
        if (c + 1 < nch) ldg((c + 1) * BK);
#pragma unroll
        for (int kk = 0; kk < BK; kk++){
            uint64_t a2[4];
#pragma unroll
            for (int i = 0; i < 4; i++)
                a2[i] = *(const uint64_t*)&As[kk][wid * 8 + 2 * i];
            float4 b40 = *(const float4*)&Bs[kk][lane * 4];
            float4 b41 = *(const float4*)&Bs[kk][128 + lane * 4];
            uint64_t b2[8] = {pack2(b40.x), pack2(b40.y), pack2(b40.z), pack2(b40.w),
                              pack2(b41.x), pack2(b41.y), pack2(b41.z), pack2(b41.w)};
#pragma unroll
            for (int i = 0; i < 4; i++)
#pragma unroll
                for (int j = 0; j < 8; j++)
                    ffma2(acc2[i][j], a2[i], b2[j]);
        }
        __syncthreads();
    }

#pragma unroll
    for (int i = 0; i < 4; i++){
#pragma unroll
        for (int h2 = 0; h2 < 2; h2++){
            const int r = bm + wid * 8 + i * 2 + h2;
#pragma unroll
            for (int grp = 0; grp < 2; grp++){
                const int col = bn + grp * 128 + lane * 4;
                float4 o; float* po = &o.x;
#pragma unroll
                for (int u = 0; u < 4; u++){
                    float2 p; memcpy(&p, &acc2[i][grp * 4 + u], 8);
                    float v = h2 ? p.y : p.x;
                    v += bias[col + u];
                    po[u] = v;
                }
                *(float4*)(C + (long)r * ldc + col) = o;
            }
        }
    }
}

// ---------------- fused scores (z=0..7, BT) + gate (z=8, silu) ----------------
__global__ __launch_bounds__(512) void scores_gate_kernel(
    const float* __restrict__ qm, const float* __restrict__ keys,
    const float* __restrict__ x,  const float* __restrict__ Ws,
    const float* __restrict__ bs, float* __restrict__ scores, float* __restrict__ gate)
{
    constexpr int BM = 128, BN = 256, BK = 16;
    __shared__ float As[BK][BM];
    __shared__ float Bs[BK][BN];

    const bool isg = (blockIdx.z == 8);
    const float* A = isg ? x    : qm   + (long)blockIdx.z * 256;
    const float* B = isg ? Ws   : keys + (long)blockIdx.z * 512 * 256;
    float*       C = isg ? gate : scores + (long)blockIdx.z * 512;
    const int K   = isg ? 1024 : 256;
    const int lda = isg ? 1024 : 2048;
    const int ldb = isg ? 512  : 256;
    const int ldc = isg ? 512  : 4096;
    const bool bt = !isg;                  // scores: B is [N][K] (keys)

    const int bm = blockIdx.y * BM, bn = blockIdx.x * BN;
    const int tid = threadIdx.x;
    const int lane = tid & 31, wid = tid >> 5;

    uint64_t acc2[4][8];
#pragma unroll
    for (int i = 0; i < 4; i++)
#pragma unroll
        for (int j = 0; j < 8; j++) acc2[i][j] = 0ull;

    const int ar = tid >> 2, ac = (tid & 3) * 4;
    float4 ra, rb0, rb1;
    auto ldg = [&](int k0){
        ra = *(const float4*)(A + (long)(bm + ar) * lda + k0 + ac);
        if (bt){
            rb0 = *(const float4*)(B + (long)(bn + ar) * ldb + k0 + ac);
            rb1 = *(const float4*)(B + (long)(bn + ar + 128) * ldb + k0 + ac);
        } else {
            const int bk = tid >> 6, bc = (tid & 63) * 4;
            rb0 = *(const float4*)(B + (long)(k0 + bk) * ldb + bn + bc);
            rb1 = *(const float4*)(B + (long)(k0 + bk + 8) * ldb + bn + bc);
        }
    };
    auto sts = [&](){
        As[ac + 0][ar] = ra.x; As[ac + 1][ar] = ra.y;
        As[ac + 2][ar] = ra.z; As[ac + 3][ar] = ra.w;
        if (bt){
            Bs[ac + 0][ar] = rb0.x; Bs[ac + 1][ar] = rb0.y;
            Bs[ac + 2][ar] = rb0.z; Bs[ac + 3][ar] = rb0.w;
            Bs[ac + 0][ar + 128] = rb1.x; Bs[ac + 1][ar + 128] = rb1.y;
            Bs[ac + 2][ar + 128] = rb1.z; Bs[ac + 3][ar + 128] = rb1.w;
        } else {
            const int bk = tid >> 6, bc = (tid & 63) * 4;
            *(float4*)&Bs[bk][bc]     = rb0;
            *(float4*)&Bs[bk + 8][bc] = rb1;
        }
    };

    const int nch = K / BK;
    ldg(0);
    for (int c = 0; c < nch; c++){
        sts();
        __syncthreads();
        if (c + 1 < nch) ldg((c + 1) * BK);
#pragma unroll
        for (int kk = 0; kk < BK; kk++){
            uint64_t a2[4];
#pragma unroll
            for (int i = 0; i < 4; i++)
                a2[i] = *(const uint64_t*)&As[kk][wid * 8 + 2 * i];
            float4 b40 = *(const float4*)&Bs[kk][lane * 4];
            float4 b41 = *(const float4*)&Bs[kk][128 + lane * 4];
            uint64_t b2[8] = {pack2(b40.x), pack2(b40.y), pack2(b40.z), pack2(b40.w),
                              pack2(b41.x), pack2(b41.y), pack2(b41.z), pack2(b41.w)};
#pragma unroll
            for (int i = 0; i < 4; i++)
#pragma unroll
                for (int j = 0; j < 8; j++)
                    ffma2(acc2[i][j], a2[i], b2[j]);
        }
        __syncthreads();
    }

#pragma unroll
    for (int i = 0; i < 4; i++){
#pragma unroll
        for (int h2 = 0; h2 < 2; h2++){
            const int r = bm + wid * 8 + i * 2 + h2;
#pragma unroll
            for (int grp = 0; grp < 2; grp++){
                const int col = bn + grp * 128 + lane * 4;
                float4 o; float* po = &o.x;
#pragma unroll
                for (int u = 0; u < 4; u++){
                    float2 p; memcpy(&p, &acc2[i][grp * 4 + u], 8);
                    float v = h2 ? p.y : p.x;
                    if (isg){ v += bs[col + u]; v = v / (1.0f + expf(-v)); }
                    po[u] = v;
                }
                *(float4*)(C + (long)r * ldc + col) = o;
            }
        }
    }
}

// ---------------- HMMA 2-split out-GEMM: C = A @ B^T + bias ----------------
__global__ __launch_bounds__(256, 1) void gemm_mma_out(
    const bf16* __restrict__ A0, const bf16* __restrict__ A1,
    const bf16* __restrict__ B0, const bf16* __restrict__ B1,
    const float* __restrict__ bias, float* __restrict__ C,
    int K, int lda, int ldb, int ldc)
{
    extern __shared__ char dsm[];
    const int tid = threadIdx.x, wid = tid >> 5, lane = tid & 31;
    const int wm = wid & 1, wn = wid >> 1;
    const int bm = blockIdx.y * 128, bn = blockIdx.x * 128;
    const bf16* As[2] = {A0, A1};
    const bf16* Bs[2] = {B0, B1};

    uint32_t sb = (smem_u32(dsm) + 1023u) & ~1023u;
    const int nch = K >> 6;

    auto load_tile = [&](uint32_t st, const bf16* g, int ld, int c0){
#pragma unroll
        for (int t = 0; t < 4; t++){
            int c = tid + t * 256, r = c >> 3, c8 = c & 7;
            cp16(st + (uint32_t)(r * 128) + (uint32_t)(((c8 ^ (r & 7)) * 16)),
                 g + (size_t)r * ld + c0 + c8 * 8);
        }
    };
    auto load_chunk = [&](int stage, int k0){
        uint32_t st = sb + stage * 65536u;
#pragma unroll
        for (int sp = 0; sp < 2; sp++) load_tile(st + sp * 16384, As[sp] + (size_t)bm * lda, lda, k0);
#pragma unroll
        for (int sp = 0; sp < 2; sp++) load_tile(st + (2 + sp) * 16384, Bs[sp] + (size_t)bn * ldb, ldb, k0);
        cp_commit();
    };

    float acc[4][4][4];
#pragma unroll
    for (int i = 0; i < 4; i++)
#pragma unroll
        for (int j = 0; j < 4; j++)
#pragma unroll
            for (int u = 0; u < 4; u++) acc[i][j][u] = 0.0f;

    const int lr = lane & 15, lk = lane >> 4;

    load_chunk(0, 0);
    for (int c = 0; c < nch; c++){
        const int s = c & 1;
        if (c + 1 < nch){ load_chunk((c + 1) & 1, (c + 1) << 6); cp_wait<1>(); }
        else cp_wait<0>();
        __syncthreads();

        const uint32_t stg = sb + s * 65536u;
#pragma unroll
        for (int ks = 0; ks < 4; ks++){
            const int kc = ks * 2 + lk;
            uint32_t af[2][4][4], bfr[2][2][4];
#pragma unroll
            for (int sp = 0; sp < 2; sp++)
#pragma unroll
                for (int i = 0; i < 4; i++){
                    int r = wm * 64 + i * 16 + lr;
                    ldsm4(af[sp][i], stg + sp * 16384 + (uint32_t)(r * 128) + (uint32_t)(((kc ^ (r & 7)) * 16)));
                }
#pragma unroll
            for (int sp = 0; sp < 2; sp++)
#pragma unroll
                for (int j2 = 0; j2 < 2; j2++){
                    int rn = wn * 32 + j2 * 16 + lr;
                    ldsm4(bfr[sp][j2], stg + (2 + sp) * 16384 + (uint32_t)(rn * 128) + (uint32_t)(((kc ^ (rn & 7)) * 16)));
                }
#pragma unroll
            for (int i = 0; i < 4; i++)
#pragma unroll
                for (int j2 = 0; j2 < 2; j2++){
                    mma16816(acc[i][2*j2],   af[0][i], bfr[0][j2][0], bfr[0][j2][2]);
                    mma16816(acc[i][2*j2+1], af[0][i], bfr[0][j2][1], bfr[0][j2][3]);
                    mma16816(acc[i][2*j2],   af[0][i], bfr[1][j2][0], bfr[1][j2][2]);
                    mma16816(acc[i][2*j2+1], af[0][i], bfr[1][j2][1], bfr[1][j2][3]);
                    mma16816(acc[i][2*j2],   af[1][i], bfr[0][j2][0], bfr[0][j2][2]);
                    mma16816(acc[i][2*j2+1], af[1][i], bfr[0][j2][1], bfr[0][j2][3]);
                }
        }
        __syncthreads();
    }

    const int tr = lane >> 2, tc = (lane & 3) * 2;
#pragma unroll
    for (int i = 0; i < 4; i++)
#pragma unroll
        for (int h2 = 0; h2 < 2; h2++){
            const int row = bm + wm * 64 + i * 16 + tr + h2 * 8;
#pragma unroll
            for (int j = 0; j < 4; j++){
                const int col = bn + wn * 32 + j * 8 + tc;
                float v0 = acc[i][j][h2*2] + bias[col];
                float v1 = acc[i][j][h2*2+1] + bias[col+1];
                *(float2*)(C + (size_t)row * ldc + col) = make_float2(v0, v1);
            }
        }
}

// ---------------- prep: Wv [K][N] -> wv2 splits [N][K] ----------------
__global__ void tsplit_kernel(const float* __restrict__ in,
    bf16* __restrict__ o0, bf16* __restrict__ o1, int K, int N)
{
    __shared__ float t[32][33];
    int k0 = blockIdx.y * 32, n0 = blockIdx.x * 32;
    t[threadIdx.y][threadIdx.x] = in[(size_t)(k0 + threadIdx.y) * N + n0 + threadIdx.x];
    __syncthreads();
    float v = t[threadIdx.x][threadIdx.y];
    size_t o = (size_t)(n0 + threadIdx.y) * K + k0 + threadIdx.x;
    bf16 h, l; split2v(v, h, l);
    o0[o] = h; o1[o] = l;
}

// ---------------- fused topk1 + topk2 + gather (one block per token) ----------------
__constant__ unsigned short c_cand[128] = {
    0x000,0x001,0x002,0x003,0x004,0x005,0x006,0x007,0x008,0x009,0x00A,0x00B,0x00C,0x00D,0x00E,0x00F,
    0x010,0x011,0x012,0x013,0x014,0x015,0x016,0x017,0x018,0x019,0x01A,0x01B,0x01C,0x01D,0x01E,0x01F,
    0x100,0x101,0x102,0x103,0x104,0x105,0x106,0x107,0x108,0x109,0x10A,0x10B,0x10C,0x10D,0x10E,0x10F,
    0x200,0x201,0x202,0x203,0x204,0x205,0x206,0x207,0x208,0x209,
    0x300,0x301,0x302,0x303,0x304,0x305,0x306,0x307,
    0x400,0x401,0x402,0x403,0x404,0x405,
    0x500,0x501,0x502,0x503,0x504,
    0x600,0x601,0x602,0x603,
    0x700,0x701,0x702,0x703,
    0x800,0x801,0x802, 0x900,0x901,0x902,
    0xA00,0xA01, 0xB00,0xB01, 0xC00,0xC01, 0xD00,0xD01, 0xE00,0xE01, 0xF00,0xF01,
    0x1000,0x1100,0x1200,0x1300,0x1400,0x1500,0x1600,0x1700,
    0x1800,0x1900,0x1A00,0x1B00,0x1C00,0x1D00,0x1E00,0x1F00,
    0xFFFF,0xFFFF,0xFFFF,0xFFFF,0xFFFF,0xFFFF,0xFFFF,0xFFFF,0xFFFF };

__global__ __launch_bounds__(256) void topk_gather_kernel(const float* __restrict__ values)
{
    const int n = blockIdx.x;
    const int tid = threadIdx.x;
    const int wid = tid >> 5, lane = tid & 31;
    const unsigned FULL = 0xffffffffu;

    __shared__ float s_ts[8][32];
    __shared__ int   s_ti[8][32];
    __shared__ unsigned long long skeys[4][128];
    __shared__ float s_cw[128];
    __shared__ int   s_ci[128];

    // ---- stage 1: all 8 warps, top-32 of 512 per (n, ht=wid) ----
    {
        const float* sc = g_scores + (size_t)n * 4096 + (size_t)wid * 512;
        float v[16]; float lmax = -FLT_MAX; int lslot = 0;
#pragma unroll
        for (int i = 0; i < 16; i++){
            v[i] = sc[i * 32 + lane];
            if (v[i] > lmax){ lmax = v[i]; lslot = i; }
        }
        float outV = 0.0f; int outI = 0;
        for (int it = 0; it < 32; it++){
            float m = lmax; int mk = lslot * 32 + lane;
#pragma unroll
            for (int off = 16; off; off >>= 1){
                float om = __shfl_xor_sync(FULL, m, off);
                int   ok = __shfl_xor_sync(FULL, mk, off);
                if (om > m || (om == m && ok < mk)){ m = om; mk = ok; }
            }
            if (lane == it){ outV = m; outI = mk; }
            if ((mk & 31) == lane){
                int ds = mk >> 5;
#pragma unroll
                for (int i = 0; i < 16; i++) if (i == ds) v[i] = -FLT_MAX;
                lmax = -FLT_MAX; lslot = 0;
#pragma unroll
                for (int i = 0; i < 16; i++) if (v[i] > lmax){ lmax = v[i]; lslot = i; }
            }
        }
        s_ts[wid][lane] = outV;
        s_ti[wid][lane] = outI;
    }
    __syncthreads();

    // ---- stage 2: warps 0-3, dominance pruning + counting selection + softmax ----
    if (wid < 4){
        const int h = wid;
        float s1 = s_ts[h * 2][lane];
        float s2 = s_ts[h * 2 + 1][lane];

        float val[4]; unsigned long long key[4]; int ci_[4], cj_[4]; bool real[4];
#pragma unroll
        for (int s = 0; s < 4; s++){
            unsigned pk = c_cand[lane * 4 + s];
            int ci = (pk >> 8) & 31, cj = pk & 31;
            ci_[s] = ci; cj_[s] = cj;
            real[s] = (pk != 0xFFFFu);
            float v = __shfl_sync(FULL, s1, ci) + __shfl_sync(FULL, s2, cj);
            val[s] = v;
            unsigned u = __float_as_uint(v);
            unsigned sv = (u & 0x80000000u) ? ~u : (u | 0x80000000u);
            unsigned p = (unsigned)(ci * 32 + cj);
            key[s] = real[s] ? (((unsigned long long)sv << 32) | (unsigned long long)(1023u - p)) : 0ull;
            skeys[h][lane * 4 + s] = key[s];
        }
        __syncwarp();

        int cnt[4] = {0,0,0,0};
        for (int k2 = 0; k2 < 128; k2++){
            unsigned long long o = skeys[h][k2];
#pragma unroll
            for (int s = 0; s < 4; s++) cnt[s] += (o > key[s]);
        }
        bool sel[4];
#pragma unroll
        for (int s = 0; s < 4; s++) sel[s] = real[s] && (cnt[s] < 32);

        float m = -FLT_MAX;
#pragma unroll
        for (int s = 0; s < 4; s++) if (sel[s] && val[s] > m) m = val[s];
#pragma unroll
        for (int off = 16; off; off >>= 1) m = fmaxf(m, __shfl_xor_sync(FULL, m, off));
        float e[4], sum = 0.0f;
#pragma unroll
        for (int s = 0; s < 4; s++){ e[s] = sel[s] ? expf(val[s] - m) : 0.0f; sum += e[s]; }
#pragma unroll
        for (int off = 16; off; off >>= 1) sum += __shfl_xor_sync(FULL, sum, off);

#pragma unroll
        for (int s = 0; s < 4; s++){
            if (sel[s]){
                s_cw[h * 32 + cnt[s]] = e[s] / sum;
                s_ci[h * 32 + cnt[s]] = s_ti[h * 2][ci_[s]] * 512 + s_ti[h * 2 + 1][cj_[s]];
            }
        }
    }
    __syncthreads();

    // ---- gather: all 256 threads, float2 over 512 dims ----
    float2 acc = {0.f, 0.f};
#pragma unroll 4
    for (int r = 0; r < 128; r++){
        float wr = s_cw[r];
        const float2 v = *((const float2*)(values + (size_t)s_ci[r] * 512) + tid);
        acc.x += wr * v.x; acc.y += wr * v.y;
    }
    float2 g = *((const float2*)(g_gate + (size_t)n * 512) + tid);
    float o0 = acc.x * g.x, o1 = acc.y * g.y;
    bf16 h0,l0,h1,l1;
    split2v(o0,h0,l0); split2v(o1,h1,l1);
    *(uint32_t*)(&g_h2[0][(size_t)n * 512 + tid * 2]) =
        (uint32_t)__bfloat16_as_ushort(h0) | ((uint32_t)__bfloat16_as_ushort(h1) << 16);
    *(uint32_t*)(&g_h2[1][(size_t)n * 512 + tid * 2]) =
        (uint32_t)__bfloat16_as_ushort(l0) | ((uint32_t)__bfloat16_as_ushort(l1) << 16);
}

// ---------------- launch ----------------
extern "C" void kernel_launch(void* const* d_in, const int* in_sizes, int n_in,
                              void* d_out, int out_size)
{
    const float* x      = (const float*)d_in[0];
    const float* Wq     = (const float*)d_in[1];
    const float* bq     = (const float*)d_in[2];
    const float* keys   = (const float*)d_in[3];
    const float* values = (const float*)d_in[4];
    const float* Ws     = (const float*)d_in[5];
    const float* bs     = (const float*)d_in[6];
    const float* Wv     = (const float*)d_in[7];
    const float* bv     = (const float*)d_in[8];
    float* out          = (float*)d_out;

    const int SMEM2 = 2 * 2 * 32768;
    cudaFuncSetAttribute(gemm_mma_out, cudaFuncAttributeMaxDynamicSharedMemorySize, SMEM2);

    float *q, *scores, *gate;
    bf16 *wv2[2], *h2[2];
    cudaGetSymbolAddress((void**)&q, g_q);
    cudaGetSymbolAddress((void**)&scores, g_scores);
    cudaGetSymbolAddress((void**)&gate, g_gate);
    {
        bf16* base;
        cudaGetSymbolAddress((void**)&base, g_wv2); for (int i=0;i<2;i++) wv2[i] = base + (size_t)i*1024*512;
        cudaGetSymbolAddress((void**)&base, g_h2);  for (int i=0;i<2;i++) h2[i]  = base + (size_t)i*2048*512;
    }

    // 1) q = x @ Wq + bq  (fp32, f32x2, exact)
    gemm_q<<<dim3(2048/256, 2048/128, 1), 512>>>(x, Wq, bq, q);

    // 2) scores (z=0..7) + gate (z=8) fused
    scores_gate_kernel<<<dim3(2, 16, 9), 512>>>(q, keys, x, Ws, bs, scores, gate);

    // 3) prep for out-GEMM (independent; fills serial slot)
    tsplit_kernel<<<dim3(32, 16), dim3(32, 32)>>>(Wv, wv2[0], wv2[1], 512, 1024);

    // 4) topk1 + topk2 + gather fused
    topk_gather_kernel<<<2048, 256>>>(values);

    // 5) out = hidden @ Wv + bv  (HMMA 2-split)
    gemm_mma_out<<<dim3(8,16,1), 256, SMEM2>>>(
        h2[0], h2[1], wv2[0], wv2[1], bv, out, 512, 512, 512, 1024);
}

// round 11
// speedup vs baseline: 1.6590x; 1.0516x over previous
#include <cuda_runtime.h>
#include <cuda_bf16.h>
#include <math.h>
#include <float.h>
#include <string.h>
#include <stdint.h>

#define KNN_K 32
typedef __nv_bfloat16 bf16;

// ---------------- scratch ----------------
__device__ __align__(16) float g_q[2048*2048];
__device__ __align__(16) float g_scores[2048*4096];
__device__ __align__(16) bf16 g_wv2[2][1024*512];
__device__ __align__(16) bf16 g_h2[2][2048*512];
__device__ __align__(16) float g_gate[2048*512];

// ---------------- helpers ----------------
__device__ __forceinline__ uint32_t smem_u32(const void* p){ return (uint32_t)__cvta_generic_to_shared(p); }
__device__ __forceinline__ void cp16(uint32_t dst, const void* src){
    asm volatile("cp.async.cg.shared.global [%0], [%1], 16;\n" :: "r"(dst), "l"(src));
}
__device__ __forceinline__ void cp_commit(){ asm volatile("cp.async.commit_group;\n" ::: "memory"); }
template<int N> __device__ __forceinline__ void cp_wait(){ asm volatile("cp.async.wait_group %0;\n" :: "n"(N) : "memory"); }
__device__ __forceinline__ void ldsm4(uint32_t (&r)[4], uint32_t addr){
    asm volatile("ldmatrix.sync.aligned.m8n8.x4.shared.b16 {%0,%1,%2,%3}, [%4];"
        : "=r"(r[0]), "=r"(r[1]), "=r"(r[2]), "=r"(r[3]) : "r"(addr));
}
__device__ __forceinline__ void mma16816(float (&d)[4], const uint32_t (&a)[4], uint32_t b0, uint32_t b1){
    asm volatile("mma.sync.aligned.m16n8k16.row.col.f32.bf16.bf16.f32 "
        "{%0,%1,%2,%3}, {%4,%5,%6,%7}, {%8,%9}, {%0,%1,%2,%3};"
        : "+f"(d[0]), "+f"(d[1]), "+f"(d[2]), "+f"(d[3])
        : "r"(a[0]), "r"(a[1]), "r"(a[2]), "r"(a[3]), "r"(b0), "r"(b1));
}
__device__ __forceinline__ void ffma2(uint64_t& d, uint64_t a, uint64_t b){
    asm("fma.rn.f32x2 %0, %1, %2, %3;" : "=l"(d) : "l"(a), "l"(b), "l"(d));
}
__device__ __forceinline__ uint64_t pack2(float v){
    uint64_t d; asm("mov.b64 %0, {%1, %1};" : "=l"(d) : "f"(v)); return d;
}
__device__ __forceinline__ void split2v(float v, bf16& h, bf16& l){
    h = __float2bfloat16(v);
    l = __float2bfloat16(v - __bfloat162float(h));
}
// compare-exchange (descending) + Batcher odd-even sort-8
__device__ __forceinline__ void ce(unsigned long long& a, unsigned long long& b){
    if (a < b){ unsigned long long t = a; a = b; b = t; }
}
__device__ __forceinline__ void sort8_desc(unsigned long long (&k)[8]){
    ce(k[0],k[1]); ce(k[2],k[3]); ce(k[4],k[5]); ce(k[6],k[7]);
    ce(k[0],k[2]); ce(k[1],k[3]); ce(k[4],k[6]); ce(k[5],k[7]);
    ce(k[1],k[2]); ce(k[5],k[6]);
    ce(k[0],k[4]); ce(k[1],k[5]); ce(k[2],k[6]); ce(k[3],k[7]);
    ce(k[2],k[4]); ce(k[3],k[5]);
    ce(k[1],k[2]); ce(k[3],k[4]); ce(k[5],k[6]);
}

// ---------------- q-GEMM: fp32 f32x2, 128x256 tile, 512 thr (verbatim) ------
__global__ __launch_bounds__(512) void gemm_q(
    const float* __restrict__ A, const float* __restrict__ B,
    const float* __restrict__ bias, float* __restrict__ C)
{
    constexpr int BM = 128, BN = 256, BK = 16;
    const int K = 1024, lda = 1024, ldb = 2048, ldc = 2048;
    __shared__ float As[BK][BM];
    __shared__ float Bs[BK][BN];

    const int bm = blockIdx.y * BM, bn = blockIdx.x * BN;
    const int tid = threadIdx.x;
    const int lane = tid & 31, wid = tid >> 5;

    uint64_t acc2[4][8];
#pragma unroll
    for (int i = 0; i < 4; i++)
#pragma unroll
        for (int j = 0; j < 8; j++) acc2[i][j] = 0ull;

    const int ar = tid >> 2, ac = (tid & 3) * 4;
    float4 ra, rb0, rb1;
    auto ldg = [&](int k0){
        ra = *(const float4*)(A + (long)(bm + ar) * lda + k0 + ac);
        const int bk = tid >> 6, bc = (tid & 63) * 4;
        rb0 = *(const float4*)(B + (long)(k0 + bk) * ldb + bn + bc);
        rb1 = *(const float4*)(B + (long)(k0 + bk + 8) * ldb + bn + bc);
    };
    auto sts = [&](){
        As[ac + 0][ar] = ra.x; As[ac + 1][ar] = ra.y;
        As[ac + 2][ar] = ra.z; As[ac + 3][ar] = ra.w;
        const int bk = tid >> 6, bc = (tid & 63) * 4;
        *(float4*)&Bs[bk][bc]     = rb0;
        *(float4*)&Bs[bk + 8][bc] = rb1;
    };

    const int nch = K / BK;
    ldg(0);
    for (int c = 0; c < nch; c++){
        sts();
        __syncthreads();
        if (c + 1 < nch) ldg((c + 1) * BK);
#pragma unroll
        for (int kk = 0; kk < BK; kk++){
            uint64_t a2[4];
#pragma unroll
            for (int i = 0; i < 4; i++)
                a2[i] = *(const uint64_t*)&As[kk][wid * 8 + 2 * i];
            float4 b40 = *(const float4*)&Bs[kk][lane * 4];
            float4 b41 = *(const float4*)&Bs[kk][128 + lane * 4];
            uint64_t b2[8] = {pack2(b40.x), pack2(b40.y), pack2(b40.z), pack2(b40.w),
                              pack2(b41.x), pack2(b41.y), pack2(b41.z), pack2(b41.w)};
#pragma unroll
            for (int i = 0; i < 4; i++)
#pragma unroll
                for (int j = 0; j < 8; j++)
                    ffma2(acc2[i][j], a2[i], b2[j]);
        }
        __syncthreads();
    }

#pragma unroll
    for (int i = 0; i < 4; i++){
#pragma unroll
        for (int h2 = 0; h2 < 2; h2++){
            const int r = bm + wid * 8 + i * 2 + h2;
#pragma unroll
            for (int grp = 0; grp < 2; grp++){
                const int col = bn + grp * 128 + lane * 4;
                float4 o; float* po = &o.x;
#pragma unroll
                for (int u = 0; u < 4; u++){
                    float2 p; memcpy(&p, &acc2[i][grp * 4 + u], 8);
                    float v = h2 ? p.y : p.x;
                    v += bias[col + u];
                    po[u] = v;
                }
                *(float4*)(C + (long)r * ldc + col) = o;
            }
        }
    }
}

// ---------------- fused scores (z=0..7, BT) + gate (z=8, silu) (verbatim) ----------------
__global__ __launch_bounds__(512) void scores_gate_kernel(
    const float* __restrict__ qm, const float* __restrict__ keys,
    const float* __restrict__ x,  const float* __restrict__ Ws,
    const float* __restrict__ bs, float* __restrict__ scores, float* __restrict__ gate)
{
    constexpr int BM = 128, BN = 256, BK = 16;
    __shared__ float As[BK][BM];
    __shared__ float Bs[BK][BN];

    const bool isg = (blockIdx.z == 8);
    const float* A = isg ? x    : qm   + (long)blockIdx.z * 256;
    const float* B = isg ? Ws   : keys + (long)blockIdx.z * 512 * 256;
    float*       C = isg ? gate : scores + (long)blockIdx.z * 512;
    const int K   = isg ? 1024 : 256;
    const int lda = isg ? 1024 : 2048;
    const int ldb = isg ? 512  : 256;
    const int ldc = isg ? 512  : 4096;
    const bool bt = !isg;

    const int bm = blockIdx.y * BM, bn = blockIdx.x * BN;
    const int tid = threadIdx.x;
    const int lane = tid & 31, wid = tid >> 5;

    uint64_t acc2[4][8];
#pragma unroll
    for (int i = 0; i < 4; i++)
#pragma unroll
        for (int j = 0; j < 8; j++) acc2[i][j] = 0ull;

    const int ar = tid >> 2, ac = (tid & 3) * 4;
    float4 ra, rb0, rb1;
    auto ldg = [&](int k0){
        ra = *(const float4*)(A + (long)(bm + ar) * lda + k0 + ac);
        if (bt){
            rb0 = *(const float4*)(B + (long)(bn + ar) * ldb + k0 + ac);
            rb1 = *(const float4*)(B + (long)(bn + ar + 128) * ldb + k0 + ac);
        } else {
            const int bk = tid >> 6, bc = (tid & 63) * 4;
            rb0 = *(const float4*)(B + (long)(k0 + bk) * ldb + bn + bc);
            rb1 = *(const float4*)(B + (long)(k0 + bk + 8) * ldb + bn + bc);
        }
    };
    auto sts = [&](){
        As[ac + 0][ar] = ra.x; As[ac + 1][ar] = ra.y;
        As[ac + 2][ar] = ra.z; As[ac + 3][ar] = ra.w;
        if (bt){
            Bs[ac + 0][ar] = rb0.x; Bs[ac + 1][ar] = rb0.y;
            Bs[ac + 2][ar] = rb0.z; Bs[ac + 3][ar] = rb0.w;
            Bs[ac + 0][ar + 128] = rb1.x; Bs[ac + 1][ar + 128] = rb1.y;
            Bs[ac + 2][ar + 128] = rb1.z; Bs[ac + 3][ar + 128] = rb1.w;
        } else {
            const int bk = tid >> 6, bc = (tid & 63) * 4;
            *(float4*)&Bs[bk][bc]     = rb0;
            *(float4*)&Bs[bk + 8][bc] = rb1;
        }
    };

    const int nch = K / BK;
    ldg(0);
    for (int c = 0; c < nch; c++){
        sts();
        __syncthreads();
        if (c + 1 < nch) ldg((c + 1) * BK);
#pragma unroll
        for (int kk = 0; kk < BK; kk++){
            uint64_t a2[4];
#pragma unroll
            for (int i = 0; i < 4; i++)
                a2[i] = *(const uint64_t*)&As[kk][wid * 8 + 2 * i];
            float4 b40 = *(const float4*)&Bs[kk][lane * 4];
            float4 b41 = *(const float4*)&Bs[kk][128 + lane * 4];
            uint64_t b2[8] = {pack2(b40.x), pack2(b40.y), pack2(b40.z), pack2(b40.w),
                              pack2(b41.x), pack2(b41.y), pack2(b41.z), pack2(b41.w)};
#pragma unroll
            for (int i = 0; i < 4; i++)
#pragma unroll
                for (int j = 0; j < 8; j++)
                    ffma2(acc2[i][j], a2[i], b2[j]);
        }
        __syncthreads();
    }

#pragma unroll
    for (int i = 0; i < 4; i++){
#pragma unroll
        for (int h2 = 0; h2 < 2; h2++){
            const int r = bm + wid * 8 + i * 2 + h2;
#pragma unroll
            for (int grp = 0; grp < 2; grp++){
                const int col = bn + grp * 128 + lane * 4;
                float4 o; float* po = &o.x;
#pragma unroll
                for (int u = 0; u < 4; u++){
                    float2 p; memcpy(&p, &acc2[i][grp * 4 + u], 8);
                    float v = h2 ? p.y : p.x;
                    if (isg){ v += bs[col + u]; v = v / (1.0f + expf(-v)); }
                    po[u] = v;
                }
                *(float4*)(C + (long)r * ldc + col) = o;
            }
        }
    }
}

// ---------------- HMMA 2-split out-GEMM (verbatim) ----------------
__global__ __launch_bounds__(256, 1) void gemm_mma_out(
    const bf16* __restrict__ A0, const bf16* __restrict__ A1,
    const bf16* __restrict__ B0, const bf16* __restrict__ B1,
    const float* __restrict__ bias, float* __restrict__ C,
    int K, int lda, int ldb, int ldc)
{
    extern __shared__ char dsm[];
    const int tid = threadIdx.x, wid = tid >> 5, lane = tid & 31;
    const int wm = wid & 1, wn = wid >> 1;
    const int bm = blockIdx.y * 128, bn = blockIdx.x * 128;
    const bf16* As[2] = {A0, A1};
    const bf16* Bs[2] = {B0, B1};

    uint32_t sb = (smem_u32(dsm) + 1023u) & ~1023u;
    const int nch = K >> 6;

    auto load_tile = [&](uint32_t st, const bf16* g, int ld, int c0){
#pragma unroll
        for (int t = 0; t < 4; t++){
            int c = tid + t * 256, r = c >> 3, c8 = c & 7;
            cp16(st + (uint32_t)(r * 128) + (uint32_t)(((c8 ^ (r & 7)) * 16)),
                 g + (size_t)r * ld + c0 + c8 * 8);
        }
    };
    auto load_chunk = [&](int stage, int k0){
        uint32_t st = sb + stage * 65536u;
#pragma unroll
        for (int sp = 0; sp < 2; sp++) load_tile(st + sp * 16384, As[sp] + (size_t)bm * lda, lda, k0);
#pragma unroll
        for (int sp = 0; sp < 2; sp++) load_tile(st + (2 + sp) * 16384, Bs[sp] + (size_t)bn * ldb, ldb, k0);
        cp_commit();
    };

    float acc[4][4][4];
#pragma unroll
    for (int i = 0; i < 4; i++)
#pragma unroll
        for (int j = 0; j < 4; j++)
#pragma unroll
            for (int u = 0; u < 4; u++) acc[i][j][u] = 0.0f;

    const int lr = lane & 15, lk = lane >> 4;

    load_chunk(0, 0);
    for (int c = 0; c < nch; c++){
        const int s = c & 1;
        if (c + 1 < nch){ load_chunk((c + 1) & 1, (c + 1) << 6); cp_wait<1>(); }
        else cp_wait<0>();
        __syncthreads();

        const uint32_t stg = sb + s * 65536u;
#pragma unroll
        for (int ks = 0; ks < 4; ks++){
            const int kc = ks * 2 + lk;
            uint32_t af[2][4][4], bfr[2][2][4];
#pragma unroll
            for (int sp = 0; sp < 2; sp++)
#pragma unroll
                for (int i = 0; i < 4; i++){
                    int r = wm * 64 + i * 16 + lr;
                    ldsm4(af[sp][i], stg + sp * 16384 + (uint32_t)(r * 128) + (uint32_t)(((kc ^ (r & 7)) * 16)));
                }
#pragma unroll
            for (int sp = 0; sp < 2; sp++)
#pragma unroll
                for (int j2 = 0; j2 < 2; j2++){
                    int rn = wn * 32 + j2 * 16 + lr;
                    ldsm4(bfr[sp][j2], stg + (2 + sp) * 16384 + (uint32_t)(rn * 128) + (uint32_t)(((kc ^ (rn & 7)) * 16)));
                }
#pragma unroll
            for (int i = 0; i < 4; i++)
#pragma unroll
                for (int j2 = 0; j2 < 2; j2++){
                    mma16816(acc[i][2*j2],   af[0][i], bfr[0][j2][0], bfr[0][j2][2]);
                    mma16816(acc[i][2*j2+1], af[0][i], bfr[0][j2][1], bfr[0][j2][3]);
                    mma16816(acc[i][2*j2],   af[0][i], bfr[1][j2][0], bfr[1][j2][2]);
                    mma16816(acc[i][2*j2+1], af[0][i], bfr[1][j2][1], bfr[1][j2][3]);
                    mma16816(acc[i][2*j2],   af[1][i], bfr[0][j2][0], bfr[0][j2][2]);
                    mma16816(acc[i][2*j2+1], af[1][i], bfr[0][j2][1], bfr[0][j2][3]);
                }
        }
        __syncthreads();
    }

    const int tr = lane >> 2, tc = (lane & 3) * 2;
#pragma unroll
    for (int i = 0; i < 4; i++)
#pragma unroll
        for (int h2 = 0; h2 < 2; h2++){
            const int row = bm + wm * 64 + i * 16 + tr + h2 * 8;
#pragma unroll
            for (int j = 0; j < 4; j++){
                const int col = bn + wn * 32 + j * 8 + tc;
                float v0 = acc[i][j][h2*2] + bias[col];
                float v1 = acc[i][j][h2*2+1] + bias[col+1];
                *(float2*)(C + (size_t)row * ldc + col) = make_float2(v0, v1);
            }
        }
}

// ---------------- prep: Wv [K][N] -> wv2 splits [N][K] ----------------
__global__ void tsplit_kernel(const float* __restrict__ in,
    bf16* __restrict__ o0, bf16* __restrict__ o1, int K, int N)
{
    __shared__ float t[32][33];
    int k0 = blockIdx.y * 32, n0 = blockIdx.x * 32;
    t[threadIdx.y][threadIdx.x] = in[(size_t)(k0 + threadIdx.y) * N + n0 + threadIdx.x];
    __syncthreads();
    float v = t[threadIdx.x][threadIdx.y];
    size_t o = (size_t)(n0 + threadIdx.y) * K + k0 + threadIdx.x;
    bf16 h, l; split2v(v, h, l);
    o0[o] = h; o1[o] = l;
}

// ---------------- fused topk1(sorted-merge) + topk2 + gather ----------------
__constant__ unsigned short c_cand[128] = {
    0x000,0x001,0x002,0x003,0x004,0x005,0x006,0x007,0x008,0x009,0x00A,0x00B,0x00C,0x00D,0x00E,0x00F,
    0x010,0x011,0x012,0x013,0x014,0x015,0x016,0x017,0x018,0x019,0x01A,0x01B,0x01C,0x01D,0x01E,0x01F,
    0x100,0x101,0x102,0x103,0x104,0x105,0x106,0x107,0x108,0x109,0x10A,0x10B,0x10C,0x10D,0x10E,0x10F,
    0x200,0x201,0x202,0x203,0x204,0x205,0x206,0x207,0x208,0x209,
    0x300,0x301,0x302,0x303,0x304,0x305,0x306,0x307,
    0x400,0x401,0x402,0x403,0x404,0x405,
    0x500,0x501,0x502,0x503,0x504,
    0x600,0x601,0x602,0x603,
    0x700,0x701,0x702,0x703,
    0x800,0x801,0x802, 0x900,0x901,0x902,
    0xA00,0xA01, 0xB00,0xB01, 0xC00,0xC01, 0xD00,0xD01, 0xE00,0xE01, 0xF00,0xF01,
    0x1000,0x1100,0x1200,0x1300,0x1400,0x1500,0x1600,0x1700,
    0x1800,0x1900,0x1A00,0x1B00,0x1C00,0x1D00,0x1E00,0x1F00,
    0xFFFF,0xFFFF,0xFFFF,0xFFFF,0xFFFF,0xFFFF,0xFFFF,0xFFFF,0xFFFF };

__global__ __launch_bounds__(256) void topk_gather_kernel(const float* __restrict__ values)
{
    const int n = blockIdx.x;
    const int tid = threadIdx.x;
    const int wid = tid >> 5, lane = tid & 31;
    const unsigned FULL = 0xffffffffu;

    __shared__ float s_ts[8][32];
    __shared__ int   s_ti[8][32];
    __shared__ unsigned long long s_lists[8][16][32];   // [warp][list*8+pos][lane], 32 KB
    __shared__ unsigned long long skeys[4][128];
    __shared__ float s_cw[128];
    __shared__ int   s_ci[128];

    // ---- stage 1: sorted 8-lists + 32-pop merge with REDUX argmax ----
    {
        const float* sc = g_scores + (size_t)n * 4096 + (size_t)wid * 512;
        unsigned long long kA[8], kB[8];
#pragma unroll
        for (int i = 0; i < 8; i++){
            float v = sc[i * 32 + lane];
            unsigned u = __float_as_uint(v);
            unsigned s = (u & 0x80000000u) ? ~u : (u | 0x80000000u);
            kA[i] = ((unsigned long long)s << 32) | (unsigned long long)(1023 - (i * 32 + lane));
        }
#pragma unroll
        for (int i = 0; i < 8; i++){
            float v = sc[(i + 8) * 32 + lane];
            unsigned u = __float_as_uint(v);
            unsigned s = (u & 0x80000000u) ? ~u : (u | 0x80000000u);
            kB[i] = ((unsigned long long)s << 32) | (unsigned long long)(1023 - ((i + 8) * 32 + lane));
        }
        sort8_desc(kA);
        sort8_desc(kB);
#pragma unroll
        for (int i = 0; i < 8; i++){
            s_lists[wid][i][lane]     = kA[i];
            s_lists[wid][8 + i][lane] = kB[i];
        }
        __syncwarp();

        int pA = 1, pB = 1;
        unsigned long long hA = kA[0], hB = kB[0];
        unsigned long long out = 0ull;
        for (int it = 0; it < 32; it++){
            unsigned long long h = (hA > hB) ? hA : hB;
            unsigned hi = (unsigned)(h >> 32);
            unsigned mhi = __reduce_max_sync(FULL, hi);
            unsigned lo = (hi == mhi) ? (unsigned)(h & 1023ull) : 0u;
            unsigned mlo = __reduce_max_sync(FULL, lo);
            unsigned long long m = ((unsigned long long)mhi << 32) | (unsigned long long)mlo;
            if (lane == it) out = m;
            if (h == m){        // unique winner (keys distinct)
                if (hA == m){ hA = (pA < 8) ? s_lists[wid][pA][lane] : 0ull; pA++; }
                else        { hB = (pB < 8) ? s_lists[wid][8 + pB][lane] : 0ull; pB++; }
            }
        }
        unsigned sv = (unsigned)(out >> 32);
        unsigned ub = (sv & 0x80000000u) ? (sv & 0x7FFFFFFFu) : ~sv;
        s_ts[wid][lane] = __uint_as_float(ub);
        s_ti[wid][lane] = 1023 - (int)(out & 1023ull);
    }
    __syncthreads();

    // ---- stage 2: warps 0-3, dominance pruning + counting selection + softmax ----
    if (wid < 4){
        const int h = wid;
        float s1 = s_ts[h * 2][lane];
        float s2 = s_ts[h * 2 + 1][lane];

        float val[4]; unsigned long long key[4]; int ci_[4], cj_[4]; bool real[4];
#pragma unroll
        for (int s = 0; s < 4; s++){
            unsigned pk = c_cand[lane * 4 + s];
            int ci = (pk >> 8) & 31, cj = pk & 31;
            ci_[s] = ci; cj_[s] = cj;
            real[s] = (pk != 0xFFFFu);
            float v = __shfl_sync(FULL, s1, ci) + __shfl_sync(FULL, s2, cj);
            val[s] = v;
            unsigned u = __float_as_uint(v);
            unsigned sv = (u & 0x80000000u) ? ~u : (u | 0x80000000u);
            unsigned p = (unsigned)(ci * 32 + cj);
            key[s] = real[s] ? (((unsigned long long)sv << 32) | (unsigned long long)(1023u - p)) : 0ull;
            skeys[h][lane * 4 + s] = key[s];
        }
        __syncwarp();

        int cnt[4] = {0,0,0,0};
        for (int k2 = 0; k2 < 128; k2++){
            unsigned long long o = skeys[h][k2];
#pragma unroll
            for (int s = 0; s < 4; s++) cnt[s] += (o > key[s]);
        }
        bool sel[4];
#pragma unroll
        for (int s = 0; s < 4; s++) sel[s] = real[s] && (cnt[s] < 32);

        float m = -FLT_MAX;
#pragma unroll
        for (int s = 0; s < 4; s++) if (sel[s] && val[s] > m) m = val[s];
#pragma unroll
        for (int off = 16; off; off >>= 1) m = fmaxf(m, __shfl_xor_sync(FULL, m, off));
        float e[4], sum = 0.0f;
#pragma unroll
        for (int s = 0; s < 4; s++){ e[s] = sel[s] ? expf(val[s] - m) : 0.0f; sum += e[s]; }
#pragma unroll
        for (int off = 16; off; off >>= 1) sum += __shfl_xor_sync(FULL, sum, off);

#pragma unroll
        for (int s = 0; s < 4; s++){
            if (sel[s]){
                s_cw[h * 32 + cnt[s]] = e[s] / sum;
                s_ci[h * 32 + cnt[s]] = s_ti[h * 2][ci_[s]] * 512 + s_ti[h * 2 + 1][cj_[s]];
            }
        }
    }
    __syncthreads();

    // ---- gather: all 256 threads, float2 over 512 dims ----
    float2 acc = {0.f, 0.f};
#pragma unroll 4
    for (int r = 0; r < 128; r++){
        float wr = s_cw[r];
        const float2 v = *((const float2*)(values + (size_t)s_ci[r] * 512) + tid);
        acc.x += wr * v.x; acc.y += wr * v.y;
    }
    float2 g = *((const float2*)(g_gate + (size_t)n * 512) + tid);
    float o0 = acc.x * g.x, o1 = acc.y * g.y;
    bf16 h0,l0,h1,l1;
    split2v(o0,h0,l0); split2v(o1,h1,l1);
    *(uint32_t*)(&g_h2[0][(size_t)n * 512 + tid * 2]) =
        (uint32_t)__bfloat16_as_ushort(h0) | ((uint32_t)__bfloat16_as_ushort(h1) << 16);
    *(uint32_t*)(&g_h2[1][(size_t)n * 512 + tid * 2]) =
        (uint32_t)__bfloat16_as_ushort(l0) | ((uint32_t)__bfloat16_as_ushort(l1) << 16);
}

// ---------------- launch ----------------
extern "C" void kernel_launch(void* const* d_in, const int* in_sizes, int n_in,
                              void* d_out, int out_size)
{
    const float* x      = (const float*)d_in[0];
    const float* Wq     = (const float*)d_in[1];
    const float* bq     = (const float*)d_in[2];
    const float* keys   = (const float*)d_in[3];
    const float* values = (const float*)d_in[4];
    const float* Ws     = (const float*)d_in[5];
    const float* bs     = (const float*)d_in[6];
    const float* Wv     = (const float*)d_in[7];
    const float* bv     = (const float*)d_in[8];
    float* out          = (float*)d_out;

    const int SMEM2 = 2 * 2 * 32768;
    cudaFuncSetAttribute(gemm_mma_out, cudaFuncAttributeMaxDynamicSharedMemorySize, SMEM2);

    float *q, *scores, *gate;
    bf16 *wv2[2], *h2[2];
    cudaGetSymbolAddress((void**)&q, g_q);
    cudaGetSymbolAddress((void**)&scores, g_scores);
    cudaGetSymbolAddress((void**)&gate, g_gate);
    {
        bf16* base;
        cudaGetSymbolAddress((void**)&base, g_wv2); for (int i=0;i<2;i++) wv2[i] = base + (size_t)i*1024*512;
        cudaGetSymbolAddress((void**)&base, g_h2);  for (int i=0;i<2;i++) h2[i]  = base + (size_t)i*2048*512;
    }

    // 1) q = x @ Wq + bq  (fp32, f32x2, exact)
    gemm_q<<<dim3(2048/256, 2048/128, 1), 512>>>(x, Wq, bq, q);

    // 2) scores (z=0..7) + gate (z=8) fused
    scores_gate_kernel<<<dim3(2, 16, 9), 512>>>(q, keys, x, Ws, bs, scores, gate);

    // 3) prep for out-GEMM
    tsplit_kernel<<<dim3(32, 16), dim3(32, 32)>>>(Wv, wv2[0], wv2[1], 512, 1024);

    // 4) topk1 + topk2 + gather fused
    topk_gather_kernel<<<2048, 256>>>(values);

    // 5) out = hidden @ Wv + bv  (HMMA 2-split)
    gemm_mma_out<<<dim3(8,16,1), 256, SMEM2>>>(
        h2[0], h2[1], wv2[0], wv2[1], bv, out, 512, 512, 512, 1024);
}

// round 15
// speedup vs baseline: 1.8695x; 1.1269x over previous
#include <cuda_runtime.h>
#include <cuda_bf16.h>
#include <math.h>
#include <float.h>
#include <string.h>
#include <stdint.h>

#define KNN_K 32
typedef __nv_bfloat16 bf16;

// ---------------- scratch ----------------
__device__ __align__(16) float g_q[2048*2048];
__device__ __align__(16) float g_scores[2048*4096];
__device__ __align__(16) bf16 g_wv2[2][1024*512];
__device__ __align__(16) bf16 g_h2[2][2048*512];
__device__ __align__(16) float g_gate[2048*512];

// ---------------- helpers ----------------
__device__ __forceinline__ uint32_t smem_u32(const void* p){ return (uint32_t)__cvta_generic_to_shared(p); }
__device__ __forceinline__ void cp16(uint32_t dst, const void* src){
    asm volatile("cp.async.cg.shared.global [%0], [%1], 16;\n" :: "r"(dst), "l"(src));
}
__device__ __forceinline__ void cp_commit(){ asm volatile("cp.async.commit_group;\n" ::: "memory"); }
template<int N> __device__ __forceinline__ void cp_wait(){ asm volatile("cp.async.wait_group %0;\n" :: "n"(N) : "memory"); }
__device__ __forceinline__ void ldsm4(uint32_t (&r)[4], uint32_t addr){
    asm volatile("ldmatrix.sync.aligned.m8n8.x4.shared.b16 {%0,%1,%2,%3}, [%4];"
        : "=r"(r[0]), "=r"(r[1]), "=r"(r[2]), "=r"(r[3]) : "r"(addr));
}
__device__ __forceinline__ void mma16816(float (&d)[4], const uint32_t (&a)[4], uint32_t b0, uint32_t b1){
    asm volatile("mma.sync.aligned.m16n8k16.row.col.f32.bf16.bf16.f32 "
        "{%0,%1,%2,%3}, {%4,%5,%6,%7}, {%8,%9}, {%0,%1,%2,%3};"
        : "+f"(d[0]), "+f"(d[1]), "+f"(d[2]), "+f"(d[3])
        : "r"(a[0]), "r"(a[1]), "r"(a[2]), "r"(a[3]), "r"(b0), "r"(b1));
}
__device__ __forceinline__ void ffma2(uint64_t& d, uint64_t a, uint64_t b){
    asm("fma.rn.f32x2 %0, %1, %2, %3;" : "=l"(d) : "l"(a), "l"(b), "l"(d));
}
__device__ __forceinline__ uint64_t pack2(float v){
    uint64_t d; asm("mov.b64 %0, {%1, %1};" : "=l"(d) : "f"(v)); return d;
}
__device__ __forceinline__ void split2v(float v, bf16& h, bf16& l){
    h = __float2bfloat16(v);
    l = __float2bfloat16(v - __bfloat162float(h));
}
// compare-exchange (descending) + Batcher odd-even sort-8
__device__ __forceinline__ void ce(unsigned long long& a, unsigned long long& b){
    if (a < b){ unsigned long long t = a; a = b; b = t; }
}
__device__ __forceinline__ void sort8_desc(unsigned long long (&k)[8]){
    ce(k[0],k[1]); ce(k[2],k[3]); ce(k[4],k[5]); ce(k[6],k[7]);
    ce(k[0],k[2]); ce(k[1],k[3]); ce(k[4],k[6]); ce(k[5],k[7]);
    ce(k[1],k[2]); ce(k[5],k[6]);
    ce(k[0],k[4]); ce(k[1],k[5]); ce(k[2],k[6]); ce(k[3],k[7]);
    ce(k[2],k[4]); ce(k[3],k[5]);
    ce(k[1],k[2]); ce(k[3],k[4]); ce(k[5],k[6]);
}

// ---------------- q-GEMM: fp32 f32x2, 128x256 tile, 512 thr (verbatim) ------
__global__ __launch_bounds__(512) void gemm_q(
    const float* __restrict__ A, const float* __restrict__ B,
    const float* __restrict__ bias, float* __restrict__ C)
{
    constexpr int BM = 128, BN = 256, BK = 16;
    const int K = 1024, lda = 1024, ldb = 2048, ldc = 2048;
    __shared__ float As[BK][BM];
    __shared__ float Bs[BK][BN];

    const int bm = blockIdx.y * BM, bn = blockIdx.x * BN;
    const int tid = threadIdx.x;
    const int lane = tid & 31, wid = tid >> 5;

    uint64_t acc2[4][8];
#pragma unroll
    for (int i = 0; i < 4; i++)
#pragma unroll
        for (int j = 0; j < 8; j++) acc2[i][j] = 0ull;

    const int ar = tid >> 2, ac = (tid & 3) * 4;
    float4 ra, rb0, rb1;
    auto ldg = [&](int k0){
        ra = *(const float4*)(A + (long)(bm + ar) * lda + k0 + ac);
        const int bk = tid >> 6, bc = (tid & 63) * 4;
        rb0 = *(const float4*)(B + (long)(k0 + bk) * ldb + bn + bc);
        rb1 = *(const float4*)(B + (long)(k0 + bk + 8) * ldb + bn + bc);
    };
    auto sts = [&](){
        As[ac + 0][ar] = ra.x; As[ac + 1][ar] = ra.y;
        As[ac + 2][ar] = ra.z; As[ac + 3][ar] = ra.w;
        const int bk = tid >> 6, bc = (tid & 63) * 4;
        *(float4*)&Bs[bk][bc]     = rb0;
        *(float4*)&Bs[bk + 8][bc] = rb1;
    };

    const int nch = K / BK;
    ldg(0);
    for (int c = 0; c < nch; c++){
        sts();
        __syncthreads();
        if (c + 1 < nch) ldg((c + 1) * BK);
#pragma unroll
        for (int kk = 0; kk < BK; kk++){
            uint64_t a2[4];
#pragma unroll
            for (int i = 0; i < 4; i++)
                a2[i] = *(const uint64_t*)&As[kk][wid * 8 + 2 * i];
            float4 b40 = *(const float4*)&Bs[kk][lane * 4];
            float4 b41 = *(const float4*)&Bs[kk][128 + lane * 4];
            uint64_t b2[8] = {pack2(b40.x), pack2(b40.y), pack2(b40.z), pack2(b40.w),
                              pack2(b41.x), pack2(b41.y), pack2(b41.z), pack2(b41.w)};
#pragma unroll
            for (int i = 0; i < 4; i++)
#pragma unroll
                for (int j = 0; j < 8; j++)
                    ffma2(acc2[i][j], a2[i], b2[j]);
        }
        __syncthreads();
    }

#pragma unroll
    for (int i = 0; i < 4; i++){
#pragma unroll
        for (int h2 = 0; h2 < 2; h2++){
            const int r = bm + wid * 8 + i * 2 + h2;
#pragma unroll
            for (int grp = 0; grp < 2; grp++){
                const int col = bn + grp * 128 + lane * 4;
                float4 o; float* po = &o.x;
#pragma unroll
                for (int u = 0; u < 4; u++){
                    float2 p; memcpy(&p, &acc2[i][grp * 4 + u], 8);
                    float v = h2 ? p.y : p.x;
                    v += bias[col + u];
                    po[u] = v;
                }
                *(float4*)(C + (long)r * ldc + col) = o;
            }
        }
    }
}

// ---------------- fused gate (z=0, silu) + scores (z=1..8, BT) ----------------
// gate blocks are 4x longer (K=1024 vs 256): dispatch them FIRST to kill the tail
__global__ __launch_bounds__(512) void scores_gate_kernel(
    const float* __restrict__ qm, const float* __restrict__ keys,
    const float* __restrict__ x,  const float* __restrict__ Ws,
    const float* __restrict__ bs, float* __restrict__ scores, float* __restrict__ gate)
{
    constexpr int BM = 128, BN = 256, BK = 16;
    __shared__ float As[BK][BM];
    __shared__ float Bs[BK][BN];

    const bool isg = (blockIdx.z == 0);
    const int  zb  = blockIdx.z - 1;      // scores batch index (valid when !isg)
    const float* A = isg ? x    : qm   + (long)zb * 256;
    const float* B = isg ? Ws   : keys + (long)zb * 512 * 256;
    float*       C = isg ? gate : scores + (long)zb * 512;
    const int K   = isg ? 1024 : 256;
    const int lda = isg ? 1024 : 2048;
    const int ldb = isg ? 512  : 256;
    const int ldc = isg ? 512  : 4096;
    const bool bt = !isg;

    const int bm = blockIdx.y * BM, bn = blockIdx.x * BN;
    const int tid = threadIdx.x;
    const int lane = tid & 31, wid = tid >> 5;

    uint64_t acc2[4][8];
#pragma unroll
    for (int i = 0; i < 4; i++)
#pragma unroll
        for (int j = 0; j < 8; j++) acc2[i][j] = 0ull;

    const int ar = tid >> 2, ac = (tid & 3) * 4;
    float4 ra, rb0, rb1;
    auto ldg = [&](int k0){
        ra = *(const float4*)(A + (long)(bm + ar) * lda + k0 + ac);
        if (bt){
            rb0 = *(const float4*)(B + (long)(bn + ar) * ldb + k0 + ac);
            rb1 = *(const float4*)(B + (long)(bn + ar + 128) * ldb + k0 + ac);
        } else {
            const int bk = tid >> 6, bc = (tid & 63) * 4;
            rb0 = *(const float4*)(B + (long)(k0 + bk) * ldb + bn + bc);
            rb1 = *(const float4*)(B + (long)(k0 + bk + 8) * ldb + bn + bc);
        }
    };
    auto sts = [&](){
        As[ac + 0][ar] = ra.x; As[ac + 1][ar] = ra.y;
        As[ac + 2][ar] = ra.z; As[ac + 3][ar] = ra.w;
        if (bt){
            Bs[ac + 0][ar] = rb0.x; Bs[ac + 1][ar] = rb0.y;
            Bs[ac + 2][ar] = rb0.z; Bs[ac + 3][ar] = rb0.w;
            Bs[ac + 0][ar + 128] = rb1.x; Bs[ac + 1][ar + 128] = rb1.y;
            Bs[ac + 2][ar + 128] = rb1.z; Bs[ac + 3][ar + 128] = rb1.w;
        } else {
            const int bk = tid >> 6, bc = (tid & 63) * 4;
            *(float4*)&Bs[bk][bc]     = rb0;
            *(float4*)&Bs[bk + 8][bc] = rb1;
        }
    };

    const int nch = K / BK;
    ldg(0);
    for (int c = 0; c < nch; c++){
        sts();
        __syncthreads();
        if (c + 1 < nch) ldg((c + 1) * BK);
#pragma unroll
        for (int kk = 0; kk < BK; kk++){
            uint64_t a2[4];
#pragma unroll
            for (int i = 0; i < 4; i++)
                a2[i] = *(const uint64_t*)&As[kk][wid * 8 + 2 * i];
            float4 b40 = *(const float4*)&Bs[kk][lane * 4];
            float4 b41 = *(const float4*)&Bs[kk][128 + lane * 4];
            uint64_t b2[8] = {pack2(b40.x), pack2(b40.y), pack2(b40.z), pack2(b40.w),
                              pack2(b41.x), pack2(b41.y), pack2(b41.z), pack2(b41.w)};
#pragma unroll
            for (int i = 0; i < 4; i++)
#pragma unroll
                for (int j = 0; j < 8; j++)
                    ffma2(acc2[i][j], a2[i], b2[j]);
        }
        __syncthreads();
    }

#pragma unroll
    for (int i = 0; i < 4; i++){
#pragma unroll
        for (int h2 = 0; h2 < 2; h2++){
            const int r = bm + wid * 8 + i * 2 + h2;
#pragma unroll
            for (int grp = 0; grp < 2; grp++){
                const int col = bn + grp * 128 + lane * 4;
                float4 o; float* po = &o.x;
#pragma unroll
                for (int u = 0; u < 4; u++){
                    float2 p; memcpy(&p, &acc2[i][grp * 4 + u], 8);
                    float v = h2 ? p.y : p.x;
                    if (isg){ v += bs[col + u]; v = v / (1.0f + expf(-v)); }
                    po[u] = v;
                }
                *(float4*)(C + (long)r * ldc + col) = o;
            }
        }
    }
}

// ---------------- HMMA 2-split out-GEMM (verbatim) ----------------
__global__ __launch_bounds__(256, 1) void gemm_mma_out(
    const bf16* __restrict__ A0, const bf16* __restrict__ A1,
    const bf16* __restrict__ B0, const bf16* __restrict__ B1,
    const float* __restrict__ bias, float* __restrict__ C,
    int K, int lda, int ldb, int ldc)
{
    extern __shared__ char dsm[];
    const int tid = threadIdx.x, wid = tid >> 5, lane = tid & 31;
    const int wm = wid & 1, wn = wid >> 1;
    const int bm = blockIdx.y * 128, bn = blockIdx.x * 128;
    const bf16* As[2] = {A0, A1};
    const bf16* Bs[2] = {B0, B1};

    uint32_t sb = (smem_u32(dsm) + 1023u) & ~1023u;
    const int nch = K >> 6;

    auto load_tile = [&](uint32_t st, const bf16* g, int ld, int c0){
#pragma unroll
        for (int t = 0; t < 4; t++){
            int c = tid + t * 256, r = c >> 3, c8 = c & 7;
            cp16(st + (uint32_t)(r * 128) + (uint32_t)(((c8 ^ (r & 7)) * 16)),
                 g + (size_t)r * ld + c0 + c8 * 8);
        }
    };
    auto load_chunk = [&](int stage, int k0){
        uint32_t st = sb + stage * 65536u;
#pragma unroll
        for (int sp = 0; sp < 2; sp++) load_tile(st + sp * 16384, As[sp] + (size_t)bm * lda, lda, k0);
#pragma unroll
        for (int sp = 0; sp < 2; sp++) load_tile(st + (2 + sp) * 16384, Bs[sp] + (size_t)bn * ldb, ldb, k0);
        cp_commit();
    };

    float acc[4][4][4];
#pragma unroll
    for (int i = 0; i < 4; i++)
#pragma unroll
        for (int j = 0; j < 4; j++)
#pragma unroll
            for (int u = 0; u < 4; u++) acc[i][j][u] = 0.0f;

    const int lr = lane & 15, lk = lane >> 4;

    load_chunk(0, 0);
    for (int c = 0; c < nch; c++){
        const int s = c & 1;
        if (c + 1 < nch){ load_chunk((c + 1) & 1, (c + 1) << 6); cp_wait<1>(); }
        else cp_wait<0>();
        __syncthreads();

        const uint32_t stg = sb + s * 65536u;
#pragma unroll
        for (int ks = 0; ks < 4; ks++){
            const int kc = ks * 2 + lk;
            uint32_t af[2][4][4], bfr[2][2][4];
#pragma unroll
            for (int sp = 0; sp < 2; sp++)
#pragma unroll
                for (int i = 0; i < 4; i++){
                    int r = wm * 64 + i * 16 + lr;
                    ldsm4(af[sp][i], stg + sp * 16384 + (uint32_t)(r * 128) + (uint32_t)(((kc ^ (r & 7)) * 16)));
                }
#pragma unroll
            for (int sp = 0; sp < 2; sp++)
#pragma unroll
                for (int j2 = 0; j2 < 2; j2++){
                    int rn = wn * 32 + j2 * 16 + lr;
                    ldsm4(bfr[sp][j2], stg + (2 + sp) * 16384 + (uint32_t)(rn * 128) + (uint32_t)(((kc ^ (rn & 7)) * 16)));
                }
#pragma unroll
            for (int i = 0; i < 4; i++)
#pragma unroll
                for (int j2 = 0; j2 < 2; j2++){
                    mma16816(acc[i][2*j2],   af[0][i], bfr[0][j2][0], bfr[0][j2][2]);
                    mma16816(acc[i][2*j2+1], af[0][i], bfr[0][j2][1], bfr[0][j2][3]);
                    mma16816(acc[i][2*j2],   af[0][i], bfr[1][j2][0], bfr[1][j2][2]);
                    mma16816(acc[i][2*j2+1], af[0][i], bfr[1][j2][1], bfr[1][j2][3]);
                    mma16816(acc[i][2*j2],   af[1][i], bfr[0][j2][0], bfr[0][j2][2]);
                    mma16816(acc[i][2*j2+1], af[1][i], bfr[0][j2][1], bfr[0][j2][3]);
                }
        }
        __syncthreads();
    }

    const int tr = lane >> 2, tc = (lane & 3) * 2;
#pragma unroll
    for (int i = 0; i < 4; i++)
#pragma unroll
        for (int h2 = 0; h2 < 2; h2++){
            const int row = bm + wm * 64 + i * 16 + tr + h2 * 8;
#pragma unroll
            for (int j = 0; j < 4; j++){
                const int col = bn + wn * 32 + j * 8 + tc;
                float v0 = acc[i][j][h2*2] + bias[col];
                float v1 = acc[i][j][h2*2+1] + bias[col+1];
                *(float2*)(C + (size_t)row * ldc + col) = make_float2(v0, v1);
            }
        }
}

// ---------------- prep: Wv [K][N] -> wv2 splits [N][K] ----------------
__global__ void tsplit_kernel(const float* __restrict__ in,
    bf16* __restrict__ o0, bf16* __restrict__ o1, int K, int N)
{
    __shared__ float t[32][33];
    int k0 = blockIdx.y * 32, n0 = blockIdx.x * 32;
    t[threadIdx.y][threadIdx.x] = in[(size_t)(k0 + threadIdx.y) * N + n0 + threadIdx.x];
    __syncthreads();
    float v = t[threadIdx.x][threadIdx.y];
    size_t o = (size_t)(n0 + threadIdx.y) * K + k0 + threadIdx.x;
    bf16 h, l; split2v(v, h, l);
    o0[o] = h; o1[o] = l;
}

// ---------------- fused topk1(sorted-merge) + topk2 + gather ----------------
__constant__ unsigned short c_cand[128] = {
    0x000,0x001,0x002,0x003,0x004,0x005,0x006,0x007,0x008,0x009,0x00A,0x00B,0x00C,0x00D,0x00E,0x00F,
    0x010,0x011,0x012,0x013,0x014,0x015,0x016,0x017,0x018,0x019,0x01A,0x01B,0x01C,0x01D,0x01E,0x01F,
    0x100,0x101,0x102,0x103,0x104,0x105,0x106,0x107,0x108,0x109,0x10A,0x10B,0x10C,0x10D,0x10E,0x10F,
    0x200,0x201,0x202,0x203,0x204,0x205,0x206,0x207,0x208,0x209,
    0x300,0x301,0x302,0x303,0x304,0x305,0x306,0x307,
    0x400,0x401,0x402,0x403,0x404,0x405,
    0x500,0x501,0x502,0x503,0x504,
    0x600,0x601,0x602,0x603,
    0x700,0x701,0x702,0x703,
    0x800,0x801,0x802, 0x900,0x901,0x902,
    0xA00,0xA01, 0xB00,0xB01, 0xC00,0xC01, 0xD00,0xD01, 0xE00,0xE01, 0xF00,0xF01,
    0x1000,0x1100,0x1200,0x1300,0x1400,0x1500,0x1600,0x1700,
    0x1800,0x1900,0x1A00,0x1B00,0x1C00,0x1D00,0x1E00,0x1F00,
    0xFFFF,0xFFFF,0xFFFF,0xFFFF,0xFFFF,0xFFFF,0xFFFF,0xFFFF,0xFFFF };

__global__ __launch_bounds__(256) void topk_gather_kernel(const float* __restrict__ values)
{
    const int n = blockIdx.x;
    const int tid = threadIdx.x;
    const int wid = tid >> 5, lane = tid & 31;
    const unsigned FULL = 0xffffffffu;

    __shared__ float s_ts[8][32];
    __shared__ int   s_ti[8][32];
    __shared__ unsigned long long s_lists[8][16][32];
    __shared__ unsigned long long skeys[4][128];
    __shared__ float s_cw[128];
    __shared__ int   s_ci[128];

    // ---- stage 1: sorted 8-lists + 32-pop merge with REDUX argmax ----
    {
        const float* sc = g_scores + (size_t)n * 4096 + (size_t)wid * 512;
        unsigned long long kA[8], kB[8];
#pragma unroll
        for (int i = 0; i < 8; i++){
            float v = sc[i * 32 + lane];
            unsigned u = __float_as_uint(v);
            unsigned s = (u & 0x80000000u) ? ~u : (u | 0x80000000u);
            kA[i] = ((unsigned long long)s << 32) | (unsigned long long)(1023 - (i * 32 + lane));
        }
#pragma unroll
        for (int i = 0; i < 8; i++){
            float v = sc[(i + 8) * 32 + lane];
            unsigned u = __float_as_uint(v);
            unsigned s = (u & 0x80000000u) ? ~u : (u | 0x80000000u);
            kB[i] = ((unsigned long long)s << 32) | (unsigned long long)(1023 - ((i + 8) * 32 + lane));
        }
        sort8_desc(kA);
        sort8_desc(kB);
#pragma unroll
        for (int i = 0; i < 8; i++){
            s_lists[wid][i][lane]     = kA[i];
            s_lists[wid][8 + i][lane] = kB[i];
        }
        __syncwarp();

        int pA = 1, pB = 1;
        unsigned long long hA = kA[0], hB = kB[0];
        unsigned long long out = 0ull;
        for (int it = 0; it < 32; it++){
            unsigned long long h = (hA > hB) ? hA : hB;
            unsigned hi = (unsigned)(h >> 32);
            unsigned mhi = __reduce_max_sync(FULL, hi);
            unsigned lo = (hi == mhi) ? (unsigned)(h & 1023ull) : 0u;
            unsigned mlo = __reduce_max_sync(FULL, lo);
            unsigned long long m = ((unsigned long long)mhi << 32) | (unsigned long long)mlo;
            if (lane == it) out = m;
            if (h == m){
                if (hA == m){ hA = (pA < 8) ? s_lists[wid][pA][lane] : 0ull; pA++; }
                else        { hB = (pB < 8) ? s_lists[wid][8 + pB][lane] : 0ull; pB++; }
            }
        }
        unsigned sv = (unsigned)(out >> 32);
        unsigned ub = (sv & 0x80000000u) ? (sv & 0x7FFFFFFFu) : ~sv;
        s_ts[wid][lane] = __uint_as_float(ub);
        s_ti[wid][lane] = 1023 - (int)(out & 1023ull);
    }
    __syncthreads();

    // ---- stage 2: warps 0-3, dominance pruning + counting selection + softmax ----
    if (wid < 4){
        const int h = wid;
        float s1 = s_ts[h * 2][lane];
        float s2 = s_ts[h * 2 + 1][lane];

        float val[4]; unsigned long long key[4]; int ci_[4], cj_[4]; bool real[4];
#pragma unroll
        for (int s = 0; s < 4; s++){
            unsigned pk = c_cand[lane * 4 + s];
            int ci = (pk >> 8) & 31, cj = pk & 31;
            ci_[s] = ci; cj_[s] = cj;
            real[s] = (pk != 0xFFFFu);
            float v = __shfl_sync(FULL, s1, ci) + __shfl_sync(FULL, s2, cj);
            val[s] = v;
            unsigned u = __float_as_uint(v);
            unsigned sv = (u & 0x80000000u) ? ~u : (u | 0x80000000u);
            unsigned p = (unsigned)(ci * 32 + cj);
            key[s] = real[s] ? (((unsigned long long)sv << 32) | (unsigned long long)(1023u - p)) : 0ull;
            skeys[h][lane * 4 + s] = key[s];
        }
        __syncwarp();

        int cnt[4] = {0,0,0,0};
        for (int k2 = 0; k2 < 128; k2++){
            unsigned long long o = skeys[h][k2];
#pragma unroll
            for (int s = 0; s < 4; s++) cnt[s] += (o > key[s]);
        }
        bool sel[4];
#pragma unroll
        for (int s = 0; s < 4; s++) sel[s] = real[s] && (cnt[s] < 32);

        float m = -FLT_MAX;
#pragma unroll
        for (int s = 0; s < 4; s++) if (sel[s] && val[s] > m) m = val[s];
#pragma unroll
        for (int off = 16; off; off >>= 1) m = fmaxf(m, __shfl_xor_sync(FULL, m, off));
        float e[4], sum = 0.0f;
#pragma unroll
        for (int s = 0; s < 4; s++){ e[s] = sel[s] ? expf(val[s] - m) : 0.0f; sum += e[s]; }
#pragma unroll
        for (int off = 16; off; off >>= 1) sum += __shfl_xor_sync(FULL, sum, off);

#pragma unroll
        for (int s = 0; s < 4; s++){
            if (sel[s]){
                s_cw[h * 32 + cnt[s]] = e[s] / sum;
                s_ci[h * 32 + cnt[s]] = s_ti[h * 2][ci_[s]] * 512 + s_ti[h * 2 + 1][cj_[s]];
            }
        }
    }
    __syncthreads();

    // ---- gather: all 256 threads, float2 over 512 dims, 2 indep chains (MLP x2) ----
    float2 acc0 = {0.f, 0.f}, acc1 = {0.f, 0.f};
#pragma unroll 4
    for (int r = 0; r < 128; r += 2){
        float w0 = s_cw[r], w1 = s_cw[r + 1];
        const float2 v0 = *((const float2*)(values + (size_t)s_ci[r] * 512) + tid);
        const float2 v1 = *((const float2*)(values + (size_t)s_ci[r + 1] * 512) + tid);
        acc0.x += w0 * v0.x; acc0.y += w0 * v0.y;
        acc1.x += w1 * v1.x; acc1.y += w1 * v1.y;
    }
    float2 g = *((const float2*)(g_gate + (size_t)n * 512) + tid);
    float o0 = (acc0.x + acc1.x) * g.x, o1 = (acc0.y + acc1.y) * g.y;
    bf16 h0,l0,h1,l1;
    split2v(o0,h0,l0); split2v(o1,h1,l1);
    *(uint32_t*)(&g_h2[0][(size_t)n * 512 + tid * 2]) =
        (uint32_t)__bfloat16_as_ushort(h0) | ((uint32_t)__bfloat16_as_ushort(h1) << 16);
    *(uint32_t*)(&g_h2[1][(size_t)n * 512 + tid * 2]) =
        (uint32_t)__bfloat16_as_ushort(l0) | ((uint32_t)__bfloat16_as_ushort(l1) << 16);
}

// ---------------- launch ----------------
extern "C" void kernel_launch(void* const* d_in, const int* in_sizes, int n_in,
                              void* d_out, int out_size)
{
    const float* x      = (const float*)d_in[0];
    const float* Wq     = (const float*)d_in[1];
    const float* bq     = (const float*)d_in[2];
    const float* keys   = (const float*)d_in[3];
    const float* values = (const float*)d_in[4];
    const float* Ws     = (const float*)d_in[5];
    const float* bs     = (const float*)d_in[6];
    const float* Wv     = (const float*)d_in[7];
    const float* bv     = (const float*)d_in[8];
    float* out          = (float*)d_out;

    const int SMEM2 = 2 * 2 * 32768;
    cudaFuncSetAttribute(gemm_mma_out, cudaFuncAttributeMaxDynamicSharedMemorySize, SMEM2);

    float *q, *scores, *gate;
    bf16 *wv2[2], *h2[2];
    cudaGetSymbolAddress((void**)&q, g_q);
    cudaGetSymbolAddress((void**)&scores, g_scores);
    cudaGetSymbolAddress((void**)&gate, g_gate);
    {
        bf16* base;
        cudaGetSymbolAddress((void**)&base, g_wv2); for (int i=0;i<2;i++) wv2[i] = base + (size_t)i*1024*512;
        cudaGetSymbolAddress((void**)&base, g_h2);  for (int i=0;i<2;i++) h2[i]  = base + (size_t)i*2048*512;
    }

    // 1) q = x @ Wq + bq  (fp32, f32x2, exact)
    gemm_q<<<dim3(2048/256, 2048/128, 1), 512>>>(x, Wq, bq, q);

    // 2) gate (z=0, long blocks first) + scores (z=1..8) fused
    scores_gate_kernel<<<dim3(2, 16, 9), 512>>>(q, keys, x, Ws, bs, scores, gate);

    // 3) prep for out-GEMM
    tsplit_kernel<<<dim3(32, 16), dim3(32, 32)>>>(Wv, wv2[0], wv2[1], 512, 1024);

    // 4) topk1 + topk2 + gather fused
    topk_gather_kernel<<<2048, 256>>>(values);

    // 5) out = hidden @ Wv + bv  (HMMA 2-split)
    gemm_mma_out<<<dim3(8,16,1), 256, SMEM2>>>(
        h2[0], h2[1], wv2[0], wv2[1], bv, out, 512, 512, 512, 1024);
}